// round 11
// baseline (speedup 1.0000x reference)
#include <cuda_runtime.h>
#include <math.h>
#include <stdint.h>

#define D      512
#define NWAY   5
#define NKPTS  17
#define BM     128
#define BN     256
#define KC     64
#define NCH    8
#define TPB    256
#define PTPB   256
#define HS     260
#define NQTILES 512

// ---- GEMM smem ----
#define SM_A      0                // 2 x 32768
#define SM_B      65536            // 2 x 65536
#define SM_TOTAL  196608

// ---- device scratch (allocation-free rule) ----
__device__ float   g_h1[25 * D];
__device__ float   g_proto[NWAY * D];
__device__ uint8_t g_W[2][NCH][65536];            // B: tf32 ldmatrix-block image
__device__ uint8_t g_Qimg[NQTILES][NCH][32768];   // A: tf32 ldmatrix-block image

// ---------------- helpers ----------------
__device__ __forceinline__ uint32_t smem_u32(const void* p) {
    uint32_t a;
    asm("{ .reg .u64 t; cvta.to.shared.u64 t, %1; cvt.u32.u64 %0, t; }" : "=r"(a) : "l"(p));
    return a;
}
__device__ __forceinline__ uint32_t f2tf32(float f) {
    uint32_t r; asm("cvt.rna.tf32.f32 %0, %1;" : "=r"(r) : "f"(f)); return r;
}
__device__ __forceinline__ void cpa16(void* dst, const void* src) {
    uint32_t d = (uint32_t)__cvta_generic_to_shared(dst);
    asm volatile("cp.async.cg.shared.global [%0], [%1], 16;" :: "r"(d), "l"(src));
}
__device__ __forceinline__ void cp_commit() { asm volatile("cp.async.commit_group;"); }
__device__ __forceinline__ void cp_wait0()  { asm volatile("cp.async.wait_group 0;"); }

__device__ __forceinline__ void ldsm4(uint32_t* r, uint32_t addr) {
    asm volatile("ldmatrix.sync.aligned.m8n8.x4.shared.b16 {%0,%1,%2,%3}, [%4];"
        : "=r"(r[0]), "=r"(r[1]), "=r"(r[2]), "=r"(r[3]) : "r"(addr));
}
__device__ __forceinline__ void mma_tf32(float* d, const uint32_t* a, const uint32_t* b) {
    asm volatile("mma.sync.aligned.m16n8k8.row.col.f32.tf32.tf32.f32 "
        "{%0,%1,%2,%3},{%4,%5,%6,%7},{%8,%9},{%0,%1,%2,%3};"
        : "+f"(d[0]), "+f"(d[1]), "+f"(d[2]), "+f"(d[3])
        : "r"(a[0]), "r"(a[1]), "r"(a[2]), "r"(a[3]), "r"(b[0]), "r"(b[1]));
}

// ---------------- weight pre-convert (B image, KC=64) ----------------
// Per (y, chunk): blk = ks*64 + noct*2 + khalf, 128B = 8 n-rows x 16B k-quad.
__global__ void convW(const float* __restrict__ Wo1, const float* __restrict__ Wc1) {
    int k = blockIdx.x;           // 0..511
    int n = threadIdx.x;          // 0..511
    int y = n >> 8, nn = n & 255;
    float v = y ? Wc1[k * BN + nn] : Wo1[k * BN + nn];
    uint32_t t = f2tf32(v);
    int c = k >> 6, kin = k & 63;
    int ks = kin >> 3, kq = kin & 7, kh = kq >> 2, kp = kq & 3;
    int noct = nn >> 3, r = nn & 7;
    uint32_t off = (uint32_t)(ks * 64 + noct * 2 + kh) * 128 + r * 16 + kp * 4;
    *(uint32_t*)&g_W[y][c][off] = t;
}

// ---------------- prototype path ----------------
__global__ void proto1(const float* __restrict__ sf,
                       const float* __restrict__ W1,
                       const float* __restrict__ b1) {
    int s = blockIdx.x;
    int j = blockIdx.y * 64 + (threadIdx.x & 63);
    int kg = threadIdx.x >> 6;
    const float* srow = sf + s * D;
    float acc = 0.f;
    int k0 = kg * 128;
    #pragma unroll 8
    for (int k = k0; k < k0 + 128; k++)
        acc += srow[k] * W1[k * D + j];
    __shared__ float red[PTPB];
    red[threadIdx.x] = acc;
    __syncthreads();
    if (threadIdx.x < 64) {
        float v = red[threadIdx.x] + red[threadIdx.x + 64] + red[threadIdx.x + 128]
                + red[threadIdx.x + 192] + b1[j];
        g_h1[s * D + j] = fmaxf(v, 0.f);
    }
}

__global__ void proto2(const float* __restrict__ W2,
                       const float* __restrict__ b2,
                       float* __restrict__ proto_out) {
    int w = blockIdx.x;
    __shared__ float hsum[D];
    int t = threadIdx.x;
    for (int k = t; k < D; k += PTPB) {
        float a = 0.f;
        #pragma unroll
        for (int s = 0; s < 5; s++) a += g_h1[(w * 5 + s) * D + k];
        hsum[k] = a;
    }
    __syncthreads();
    int j = blockIdx.y * 64 + (t & 63);
    int kg = t >> 6;
    float acc = 0.f;
    int k0 = kg * 128;
    #pragma unroll 8
    for (int k = k0; k < k0 + 128; k++)
        acc += hsum[k] * W2[k * D + j];
    __shared__ float red[PTPB];
    red[t] = acc;
    __syncthreads();
    if (t < 64) {
        float p = (red[t] + red[t + 64] + red[t + 128] + red[t + 192]) * 0.2f + b2[j];
        g_proto[w * D + j] = p;
        #pragma unroll
        for (int kp = 0; kp < NKPTS; kp++)
            proto_out[(size_t)(w * NKPTS + kp) * D + j] = p;
    }
}

// ---------------- preQ: sector-optimal transform + exact distances ----------------
__global__ void __launch_bounds__(PTPB, 3)
preQ(const float* __restrict__ Q, const float* __restrict__ temp,
     float* __restrict__ dist_out, float* __restrict__ cls_out) {
    __shared__ float sproto[NWAY * D];
    __shared__ float spn[NWAY];
    __shared__ float sdist[BM * NWAY];
    __shared__ float scls[BM];

    const int tid  = threadIdx.x;
    const int warp = tid >> 5;
    const int lane = tid & 31;
    const size_t q0 = (size_t)blockIdx.x * BM;

    for (int i = tid; i < NWAY * D; i += PTPB) sproto[i] = g_proto[i];
    __syncthreads();

    if (warp < NWAY) {
        float s = 0.f;
        for (int k = lane; k < D; k += 32) { float v = sproto[warp * D + k]; s += v * v; }
        #pragma unroll
        for (int off = 16; off > 0; off >>= 1) s += __shfl_xor_sync(0xffffffffu, s, off);
        if (lane == 0) spn[warp] = sqrtf(s);
    }
    __syncthreads();

    const int rsub = lane >> 2;    // row within warp octet
    const int lq   = lane & 3;     // k-quad group
    uint8_t* img = &g_Qimg[blockIdx.x][0][0];

    #pragma unroll 1
    for (int o = 0; o < 2; o++) {
        int rowl = o * 64 + warp * 8 + rsub;       // tile-local row 0..127
        const float* qr = Q + (q0 + rowl) * D;
        const int mblk = (rowl >> 4) * 4 + ((rowl >> 3) & 1);
        const int roff = (rowl & 7) * 16;

        float qq = 0.f, s0 = 0.f, s1 = 0.f, s2 = 0.f, s3 = 0.f, s4 = 0.f;
        #pragma unroll 4
        for (int j = 0; j < 32; j++) {
            float4 v = ((const float4*)qr)[lq + j * 4];
            int k = lq * 4 + j * 16;
            {
                float4 p0 = *(const float4*)(sproto + 0 * D + k);
                float4 p1 = *(const float4*)(sproto + 1 * D + k);
                float4 p2 = *(const float4*)(sproto + 2 * D + k);
                float4 p3 = *(const float4*)(sproto + 3 * D + k);
                float4 p4 = *(const float4*)(sproto + 4 * D + k);
                qq += v.x * v.x + v.y * v.y + v.z * v.z + v.w * v.w;
                s0 += v.x * p0.x + v.y * p0.y + v.z * p0.z + v.w * p0.w;
                s1 += v.x * p1.x + v.y * p1.y + v.z * p1.z + v.w * p1.w;
                s2 += v.x * p2.x + v.y * p2.y + v.z * p2.z + v.w * p2.w;
                s3 += v.x * p3.x + v.y * p3.y + v.z * p3.z + v.w * p3.w;
                s4 += v.x * p4.x + v.y * p4.y + v.z * p4.z + v.w * p4.w;
            }
            int c  = j >> 2;
            int kk = k & 63;
            int ks = kk >> 3, kh = (kk >> 2) & 1;
            uint32_t off = (uint32_t)c * 32768u
                         + (uint32_t)(ks * 32 + kh * 2 + mblk) * 128u + roff;
            *(uint4*)(img + off) =
                make_uint4(f2tf32(v.x), f2tf32(v.y), f2tf32(v.z), f2tf32(v.w));
        }

        // reduce over the 4-lane k-group
        #pragma unroll
        for (int off = 1; off <= 2; off <<= 1) {
            qq += __shfl_xor_sync(0xffffffffu, qq, off);
            s0 += __shfl_xor_sync(0xffffffffu, s0, off);
            s1 += __shfl_xor_sync(0xffffffffu, s1, off);
            s2 += __shfl_xor_sync(0xffffffffu, s2, off);
            s3 += __shfl_xor_sync(0xffffffffu, s3, off);
            s4 += __shfl_xor_sync(0xffffffffu, s4, off);
        }
        if (lq == 0) {
            const float T = *temp;
            float qn = sqrtf(qq);
            float sv[5] = {s0, s1, s2, s3, s4};
            float best = 3.402823e38f; int bi = 0;
            #pragma unroll
            for (int w = 0; w < NWAY; w++) {
                float denom = fmaxf(qn * spn[w], 1e-8f);
                float dv = (1.0f - sv[w] / denom) / T;
                sdist[rowl * NWAY + w] = dv;
                if (dv < best) { best = dv; bi = w; }
            }
            scls[rowl] = (float)bi;
        }
    }
    __syncthreads();

    // coalesced distance outputs (warp handles 16 rows)
    for (int rr = 0; rr < 16; rr++) {
        int r = warp * 16 + rr;
        size_t qi = q0 + r;
        for (int l = lane; l < NWAY * NKPTS; l += 32)
            dist_out[qi * (NWAY * NKPTS) + l] = sdist[r * NWAY + l / NKPTS];
        if (lane == 0) cls_out[qi] = scls[r];
    }
}

// ---------------- main GEMM kernel (64x64 warp tiles; paired y CTAs) ----------------
__global__ void __launch_bounds__(TPB, 1)
query_kernel(const float* __restrict__ IC,
             const float* __restrict__ bo1, const float* __restrict__ Wo2,
             const float* __restrict__ bo2,
             const float* __restrict__ bc1, const float* __restrict__ Wc2,
             const float* __restrict__ bc2,
             float* __restrict__ kp_out, float* __restrict__ conf_out) {
    extern __shared__ char smem[];
    const uint32_t sb = smem_u32(smem);

    const int tid  = threadIdx.x;
    const int warp = tid >> 5;
    const int lane = tid & 31;
    const int g    = lane >> 2;
    const int qd   = lane & 3;
    const int tile = blockIdx.x >> 1;      // paired: y CTAs adjacent -> A image L2 reuse
    const int y    = blockIdx.x & 1;
    const size_t q0 = (size_t)tile * BM;

    const uint8_t* Asrc = &g_Qimg[tile][0][0];

    auto cpA = [&](int c, int buf) {
        const uint8_t* src = Asrc + c * 32768;
        char* dst = smem + SM_A + buf * 32768;
        #pragma unroll
        for (int i = 0; i < 8; i++) {
            int idx = (tid + i * TPB) * 16;
            cpa16(dst + idx, src + idx);
        }
    };
    auto cpB = [&](int c, int buf) {
        const uint8_t* src = &g_W[y][c][0];
        char* dst = smem + SM_B + buf * 65536;
        #pragma unroll
        for (int i = 0; i < 16; i++) {
            int idx = (tid + i * TPB) * 16;
            cpa16(dst + idx, src + idx);
        }
    };

    cpA(0, 0);
    cpB(0, 0);
    cp_commit();
    cp_wait0();
    __syncthreads();

    float acc[4][8][4];
    #pragma unroll
    for (int mi = 0; mi < 4; mi++)
        #pragma unroll
        for (int ni = 0; ni < 8; ni++)
            #pragma unroll
            for (int i = 0; i < 4; i++) acc[mi][ni][i] = 0.f;

    const int wm = (warp & 1) * 64;            // 2 m-groups of 64
    const int wn = (warp >> 1) * 64;           // 4 n-groups of 64
    const uint32_t a_mt0 = (uint32_t)((warp & 1) * 4);
    const uint32_t b_blk0 = (uint32_t)(wn >> 2);

    #pragma unroll 1
    for (int c = 0; c < NCH; c++) {
        int buf = c & 1;
        if (c < NCH - 1) {
            cpA(c + 1, buf ^ 1);
            cpB(c + 1, buf ^ 1);
            cp_commit();
        }

        uint32_t ab   = sb + SM_A + buf * 32768;
        uint32_t bbuf = sb + SM_B + buf * 65536;
        #pragma unroll
        for (int ks = 0; ks < 8; ks++) {
            uint32_t Af[4][4];
            #pragma unroll
            for (int j = 0; j < 4; j++)
                ldsm4(Af[j], ab + (uint32_t)(ks * 32 + (a_mt0 + j) * 4) * 128 + lane * 16);
            #pragma unroll
            for (int p = 0; p < 4; p++) {
                uint32_t r[4];
                ldsm4(r, bbuf + (uint32_t)(ks * 64 + b_blk0 + 4 * p) * 128 + lane * 16);
                #pragma unroll
                for (int j = 0; j < 4; j++) {
                    mma_tf32(acc[j][2 * p],     Af[j], r);
                    mma_tf32(acc[j][2 * p + 1], Af[j], r + 2);
                }
            }
        }

        if (c < NCH - 1) {
            cp_wait0();
            __syncthreads();
        }
    }
    __syncthreads();   // all smem reads done before H reuse

    // store H = relu(acc + bias)
    {
        const float* bb1 = y ? bc1 : bo1;
        float* Hs = (float*)smem;
        #pragma unroll
        for (int ni = 0; ni < 8; ni++) {
            int colb = wn + ni * 8 + 2 * qd;
            float b0v = bb1[colb], b1v = bb1[colb + 1];
            #pragma unroll
            for (int mi = 0; mi < 4; mi++) {
                int r0 = wm + mi * 16 + g;
                Hs[r0 * HS + colb]           = fmaxf(acc[mi][ni][0] + b0v, 0.f);
                Hs[r0 * HS + colb + 1]       = fmaxf(acc[mi][ni][1] + b1v, 0.f);
                Hs[(r0 + 8) * HS + colb]     = fmaxf(acc[mi][ni][2] + b0v, 0.f);
                Hs[(r0 + 8) * HS + colb + 1] = fmaxf(acc[mi][ni][3] + b1v, 0.f);
            }
        }
    }
    __syncthreads();

    // heads + outputs (warp handles 16 rows)
    const float* Hs = (const float*)smem;
    if (y == 0) {
        for (int rr = 0; rr < 16; rr++) {
            int r = warp * 16 + rr;
            size_t qi = q0 + r;
            float ox = 0.f, oy = 0.f;
            for (int i = lane; i < BN; i += 32) {
                float h = Hs[r * HS + i];
                ox += h * Wo2[2 * i];
                oy += h * Wo2[2 * i + 1];
            }
            #pragma unroll
            for (int off = 16; off > 0; off >>= 1) {
                ox += __shfl_xor_sync(0xffffffffu, ox, off);
                oy += __shfl_xor_sync(0xffffffffu, oy, off);
            }
            float kx = 0.f, ky = 0.f;
            if (lane == 0) {
                ox += bo2[0]; oy += bo2[1];
                kx = IC[qi * 2 + 0] / (1.0f + expf(-ox));
                ky = IC[qi * 2 + 1] / (1.0f + expf(-oy));
            }
            kx = __shfl_sync(0xffffffffu, kx, 0);
            ky = __shfl_sync(0xffffffffu, ky, 0);
            for (int l = lane; l < 2 * NKPTS; l += 32)
                kp_out[qi * (2 * NKPTS) + l] = (l & 1) ? ky : kx;
        }
    } else {
        for (int rr = 0; rr < 16; rr++) {
            int r = warp * 16 + rr;
            size_t qi = q0 + r;
            float cl = 0.f;
            for (int i = lane; i < BN; i += 32)
                cl += Hs[r * HS + i] * Wc2[i];
            #pragma unroll
            for (int off = 16; off > 0; off >>= 1)
                cl += __shfl_xor_sync(0xffffffffu, cl, off);
            float cf = 0.f;
            if (lane == 0)
                cf = 1.0f / (1.0f + expf(-(cl + bc2[0])));
            cf = __shfl_sync(0xffffffffu, cf, 0);
            if (lane < NKPTS)
                conf_out[qi * NKPTS + lane] = cf;
        }
    }
}

extern "C" void kernel_launch(void* const* d_in, const int* in_sizes, int n_in,
                              void* d_out, int out_size) {
    const float* sf   = (const float*)d_in[0];
    const float* Q    = (const float*)d_in[2];
    const float* IC   = (const float*)d_in[3];
    const float* W1   = (const float*)d_in[4];
    const float* b1   = (const float*)d_in[5];
    const float* W2   = (const float*)d_in[6];
    const float* b2   = (const float*)d_in[7];
    const float* Wo1  = (const float*)d_in[8];
    const float* bo1  = (const float*)d_in[9];
    const float* Wo2  = (const float*)d_in[10];
    const float* bo2  = (const float*)d_in[11];
    const float* Wc1  = (const float*)d_in[12];
    const float* bc1  = (const float*)d_in[13];
    const float* Wc2  = (const float*)d_in[14];
    const float* bc2  = (const float*)d_in[15];
    const float* temp = (const float*)d_in[16];

    const int nq = in_sizes[2] / D;

    float* out       = (float*)d_out;
    float* kp_out    = out;
    float* conf_out  = kp_out   + (size_t)nq * 2 * NKPTS;
    float* dist_out  = conf_out + (size_t)nq * NKPTS;
    float* cls_out   = dist_out + (size_t)nq * NWAY * NKPTS;
    float* proto_out = cls_out  + (size_t)nq;

    convW<<<D, 512>>>(Wo1, Wc1);
    proto1<<<dim3(25, 8), PTPB>>>(sf, W1, b1);
    proto2<<<dim3(NWAY, 8), PTPB>>>(W2, b2, proto_out);

    preQ<<<nq / BM, PTPB>>>(Q, temp, dist_out, cls_out);

    cudaFuncSetAttribute((const void*)query_kernel,
                         cudaFuncAttributeMaxDynamicSharedMemorySize, SM_TOTAL);
    query_kernel<<<(nq / BM) * 2, TPB, SM_TOTAL>>>(
        IC, bo1, Wo2, bo2, bc1, Wc2, bc2, kp_out, conf_out);
}

// round 12
// speedup vs baseline: 1.0293x; 1.0293x over previous
#include <cuda_runtime.h>
#include <math.h>
#include <stdint.h>

#define D      512
#define NWAY   5
#define NKPTS  17
#define BM     128
#define BN     256
#define KC     64
#define NCH    8
#define TPB    256
#define PTPB   256
#define HS     260
#define NQTILES 512

// ---- GEMM smem ----
#define SM_A      0                // 2 x 32768
#define SM_B      65536            // 2 x 65536
#define SM_TOTAL  196608

// ---- device scratch (allocation-free rule) ----
__device__ float   g_h1[25 * D];
__device__ float   g_proto[NWAY * D];
__device__ uint8_t g_W[2][NCH][65536];            // B: tf32 ldmatrix-block image
__device__ uint8_t g_Qimg[NQTILES][NCH][32768];   // A: tf32 ldmatrix-block image

// ---------------- helpers ----------------
__device__ __forceinline__ uint32_t smem_u32(const void* p) {
    uint32_t a;
    asm("{ .reg .u64 t; cvta.to.shared.u64 t, %1; cvt.u32.u64 %0, t; }" : "=r"(a) : "l"(p));
    return a;
}
__device__ __forceinline__ uint32_t f2tf32(float f) {
    uint32_t r; asm("cvt.rna.tf32.f32 %0, %1;" : "=r"(r) : "f"(f)); return r;
}
__device__ __forceinline__ void cpa16(void* dst, const void* src) {
    uint32_t d = (uint32_t)__cvta_generic_to_shared(dst);
    asm volatile("cp.async.cg.shared.global [%0], [%1], 16;" :: "r"(d), "l"(src));
}
__device__ __forceinline__ void cp_commit() { asm volatile("cp.async.commit_group;"); }
__device__ __forceinline__ void cp_wait0()  { asm volatile("cp.async.wait_group 0;"); }

__device__ __forceinline__ void ldsm4(uint32_t* r, uint32_t addr) {
    asm volatile("ldmatrix.sync.aligned.m8n8.x4.shared.b16 {%0,%1,%2,%3}, [%4];"
        : "=r"(r[0]), "=r"(r[1]), "=r"(r[2]), "=r"(r[3]) : "r"(addr));
}
__device__ __forceinline__ void mma_tf32(float* d, const uint32_t* a, const uint32_t* b) {
    asm volatile("mma.sync.aligned.m16n8k8.row.col.f32.tf32.tf32.f32 "
        "{%0,%1,%2,%3},{%4,%5,%6,%7},{%8,%9},{%0,%1,%2,%3};"
        : "+f"(d[0]), "+f"(d[1]), "+f"(d[2]), "+f"(d[3])
        : "r"(a[0]), "r"(a[1]), "r"(a[2]), "r"(a[3]), "r"(b[0]), "r"(b[1]));
}

// ---------------- weight pre-convert (B image, KC=64) ----------------
// Per (y, chunk): blk = ks*64 + noct*2 + khalf, 128B = 8 n-rows x 16B k-quad.
__global__ void convW(const float* __restrict__ Wo1, const float* __restrict__ Wc1) {
    int k = blockIdx.x;           // 0..511
    int n = threadIdx.x;          // 0..511
    int y = n >> 8, nn = n & 255;
    float v = y ? Wc1[k * BN + nn] : Wo1[k * BN + nn];
    uint32_t t = f2tf32(v);
    int c = k >> 6, kin = k & 63;
    int ks = kin >> 3, kq = kin & 7, kh = kq >> 2, kp = kq & 3;
    int noct = nn >> 3, r = nn & 7;
    uint32_t off = (uint32_t)(ks * 64 + noct * 2 + kh) * 128 + r * 16 + kp * 4;
    *(uint32_t*)&g_W[y][c][off] = t;
}

// ---------------- prototype path ----------------
__global__ void proto1(const float* __restrict__ sf,
                       const float* __restrict__ W1,
                       const float* __restrict__ b1) {
    int s = blockIdx.x;
    int j = blockIdx.y * 64 + (threadIdx.x & 63);
    int kg = threadIdx.x >> 6;
    const float* srow = sf + s * D;
    float acc = 0.f;
    int k0 = kg * 128;
    #pragma unroll 8
    for (int k = k0; k < k0 + 128; k++)
        acc += srow[k] * W1[k * D + j];
    __shared__ float red[PTPB];
    red[threadIdx.x] = acc;
    __syncthreads();
    if (threadIdx.x < 64) {
        float v = red[threadIdx.x] + red[threadIdx.x + 64] + red[threadIdx.x + 128]
                + red[threadIdx.x + 192] + b1[j];
        g_h1[s * D + j] = fmaxf(v, 0.f);
    }
}

__global__ void proto2(const float* __restrict__ W2,
                       const float* __restrict__ b2,
                       float* __restrict__ proto_out) {
    int w = blockIdx.x;
    __shared__ float hsum[D];
    int t = threadIdx.x;
    for (int k = t; k < D; k += PTPB) {
        float a = 0.f;
        #pragma unroll
        for (int s = 0; s < 5; s++) a += g_h1[(w * 5 + s) * D + k];
        hsum[k] = a;
    }
    __syncthreads();
    int j = blockIdx.y * 64 + (t & 63);
    int kg = t >> 6;
    float acc = 0.f;
    int k0 = kg * 128;
    #pragma unroll 8
    for (int k = k0; k < k0 + 128; k++)
        acc += hsum[k] * W2[k * D + j];
    __shared__ float red[PTPB];
    red[t] = acc;
    __syncthreads();
    if (t < 64) {
        float p = (red[t] + red[t + 64] + red[t + 128] + red[t + 192]) * 0.2f + b2[j];
        g_proto[w * D + j] = p;
        #pragma unroll
        for (int kp = 0; kp < NKPTS; kp++)
            proto_out[(size_t)(w * NKPTS + kp) * D + j] = p;
    }
}

// ---------------- preQ: sector-optimal transform + exact distances ----------------
__global__ void __launch_bounds__(PTPB, 2)
preQ(const float* __restrict__ Q, const float* __restrict__ temp,
     float* __restrict__ dist_out, float* __restrict__ cls_out) {
    __shared__ float sproto[NWAY * D];
    __shared__ float spn[NWAY];
    __shared__ float sdist[BM * NWAY];
    __shared__ float scls[BM];

    const int tid  = threadIdx.x;
    const int warp = tid >> 5;
    const int lane = tid & 31;
    const size_t q0 = (size_t)blockIdx.x * BM;

    for (int i = tid; i < NWAY * D; i += PTPB) sproto[i] = g_proto[i];
    __syncthreads();

    if (warp < NWAY) {
        float s = 0.f;
        for (int k = lane; k < D; k += 32) { float v = sproto[warp * D + k]; s += v * v; }
        #pragma unroll
        for (int off = 16; off > 0; off >>= 1) s += __shfl_xor_sync(0xffffffffu, s, off);
        if (lane == 0) spn[warp] = sqrtf(s);
    }
    __syncthreads();

    const int rsub = lane >> 2;    // row within warp octet
    const int lq   = lane & 3;     // k-quad group
    uint8_t* img = &g_Qimg[blockIdx.x][0][0];

    #pragma unroll 1
    for (int o = 0; o < 2; o++) {
        int rowl = o * 64 + warp * 8 + rsub;       // tile-local row 0..127
        const float* qr = Q + (q0 + rowl) * D;
        const int mblk = (rowl >> 4) * 4 + ((rowl >> 3) & 1);
        const int roff = (rowl & 7) * 16;

        float qq = 0.f, s0 = 0.f, s1 = 0.f, s2 = 0.f, s3 = 0.f, s4 = 0.f;
        #pragma unroll 4
        for (int j = 0; j < 32; j++) {
            float4 v = ((const float4*)qr)[lq + j * 4];
            int k = lq * 4 + j * 16;
            {
                float4 p0 = *(const float4*)(sproto + 0 * D + k);
                float4 p1 = *(const float4*)(sproto + 1 * D + k);
                float4 p2 = *(const float4*)(sproto + 2 * D + k);
                float4 p3 = *(const float4*)(sproto + 3 * D + k);
                float4 p4 = *(const float4*)(sproto + 4 * D + k);
                qq += v.x * v.x + v.y * v.y + v.z * v.z + v.w * v.w;
                s0 += v.x * p0.x + v.y * p0.y + v.z * p0.z + v.w * p0.w;
                s1 += v.x * p1.x + v.y * p1.y + v.z * p1.z + v.w * p1.w;
                s2 += v.x * p2.x + v.y * p2.y + v.z * p2.z + v.w * p2.w;
                s3 += v.x * p3.x + v.y * p3.y + v.z * p3.z + v.w * p3.w;
                s4 += v.x * p4.x + v.y * p4.y + v.z * p4.z + v.w * p4.w;
            }
            int c  = j >> 2;
            int kk = k & 63;
            int ks = kk >> 3, kh = (kk >> 2) & 1;
            uint32_t off = (uint32_t)c * 32768u
                         + (uint32_t)(ks * 32 + kh * 2 + mblk) * 128u + roff;
            *(uint4*)(img + off) =
                make_uint4(f2tf32(v.x), f2tf32(v.y), f2tf32(v.z), f2tf32(v.w));
        }

        // reduce over the 4-lane k-group
        #pragma unroll
        for (int off = 1; off <= 2; off <<= 1) {
            qq += __shfl_xor_sync(0xffffffffu, qq, off);
            s0 += __shfl_xor_sync(0xffffffffu, s0, off);
            s1 += __shfl_xor_sync(0xffffffffu, s1, off);
            s2 += __shfl_xor_sync(0xffffffffu, s2, off);
            s3 += __shfl_xor_sync(0xffffffffu, s3, off);
            s4 += __shfl_xor_sync(0xffffffffu, s4, off);
        }
        if (lq == 0) {
            const float T = *temp;
            float qn = sqrtf(qq);
            float sv[5] = {s0, s1, s2, s3, s4};
            float best = 3.402823e38f; int bi = 0;
            #pragma unroll
            for (int w = 0; w < NWAY; w++) {
                float denom = fmaxf(qn * spn[w], 1e-8f);
                float dv = (1.0f - sv[w] / denom) / T;
                sdist[rowl * NWAY + w] = dv;
                if (dv < best) { best = dv; bi = w; }
            }
            scls[rowl] = (float)bi;
        }
    }
    __syncthreads();

    // coalesced distance outputs (warp handles 16 rows)
    for (int rr = 0; rr < 16; rr++) {
        int r = warp * 16 + rr;
        size_t qi = q0 + r;
        for (int l = lane; l < NWAY * NKPTS; l += 32)
            dist_out[qi * (NWAY * NKPTS) + l] = sdist[r * NWAY + l / NKPTS];
        if (lane == 0) cls_out[qi] = scls[r];
    }
}

// ---------------- main GEMM kernel (64x64 warp tiles; pipelined fragments) ----------------
__global__ void __launch_bounds__(TPB, 1)
query_kernel(const float* __restrict__ IC,
             const float* __restrict__ bo1, const float* __restrict__ Wo2,
             const float* __restrict__ bo2,
             const float* __restrict__ bc1, const float* __restrict__ Wc2,
             const float* __restrict__ bc2,
             float* __restrict__ kp_out, float* __restrict__ conf_out) {
    extern __shared__ char smem[];
    const uint32_t sb = smem_u32(smem);

    const int tid  = threadIdx.x;
    const int warp = tid >> 5;
    const int lane = tid & 31;
    const int g    = lane >> 2;
    const int qd   = lane & 3;
    const int y    = blockIdx.y;
    const size_t q0 = (size_t)blockIdx.x * BM;

    const uint8_t* Asrc = &g_Qimg[blockIdx.x][0][0];

    auto cpA = [&](int c, int buf) {
        const uint8_t* src = Asrc + c * 32768;
        char* dst = smem + SM_A + buf * 32768;
        #pragma unroll
        for (int i = 0; i < 8; i++) {
            int idx = (tid + i * TPB) * 16;
            cpa16(dst + idx, src + idx);
        }
    };
    auto cpB = [&](int c, int buf) {
        const uint8_t* src = &g_W[y][c][0];
        char* dst = smem + SM_B + buf * 65536;
        #pragma unroll
        for (int i = 0; i < 16; i++) {
            int idx = (tid + i * TPB) * 16;
            cpa16(dst + idx, src + idx);
        }
    };

    cpA(0, 0);
    cpB(0, 0);
    cp_commit();
    cp_wait0();
    __syncthreads();

    float acc[4][8][4];
    #pragma unroll
    for (int mi = 0; mi < 4; mi++)
        #pragma unroll
        for (int ni = 0; ni < 8; ni++)
            #pragma unroll
            for (int i = 0; i < 4; i++) acc[mi][ni][i] = 0.f;

    const int wm = (warp & 1) * 64;            // 2 m-groups of 64
    const int wn = (warp >> 1) * 64;           // 4 n-groups of 64
    const uint32_t a_mt0 = (uint32_t)((warp & 1) * 4);
    const uint32_t b_blk0 = (uint32_t)(wn >> 2);

    #pragma unroll 1
    for (int c = 0; c < NCH; c++) {
        int buf = c & 1;
        if (c < NCH - 1) {
            cpA(c + 1, buf ^ 1);
            cpB(c + 1, buf ^ 1);
            cp_commit();
        }

        uint32_t ab   = sb + SM_A + buf * 32768;
        uint32_t bbuf = sb + SM_B + buf * 65536;

        // software-pipelined fragments: A double-buffered across ks,
        // B double-buffered across p (each LDSM covered by >=8 MMAs).
        uint32_t Af[2][4][4];
        uint32_t Bf[2][4];
        #pragma unroll
        for (int j = 0; j < 4; j++)
            ldsm4(Af[0][j], ab + (uint32_t)((a_mt0 + j) * 4) * 128 + lane * 16);
        ldsm4(Bf[0], bbuf + (uint32_t)b_blk0 * 128 + lane * 16);

        #pragma unroll
        for (int ks = 0; ks < 8; ks++) {
            const int cur = ks & 1;
            if (ks < 7) {
                #pragma unroll
                for (int j = 0; j < 4; j++)
                    ldsm4(Af[cur ^ 1][j],
                          ab + (uint32_t)((ks + 1) * 32 + (a_mt0 + j) * 4) * 128 + lane * 16);
            }
            #pragma unroll
            for (int p = 0; p < 4; p++) {
                const int pc = p & 1;
                if (p < 3)
                    ldsm4(Bf[pc ^ 1],
                          bbuf + (uint32_t)(ks * 64 + b_blk0 + 4 * (p + 1)) * 128 + lane * 16);
                else if (ks < 7)
                    ldsm4(Bf[pc ^ 1],
                          bbuf + (uint32_t)((ks + 1) * 64 + b_blk0) * 128 + lane * 16);
                #pragma unroll
                for (int j = 0; j < 4; j++) {
                    mma_tf32(acc[j][2 * p],     Af[cur][j], Bf[pc]);
                    mma_tf32(acc[j][2 * p + 1], Af[cur][j], Bf[pc] + 2);
                }
            }
        }

        if (c < NCH - 1) {
            cp_wait0();
            __syncthreads();
        }
    }
    __syncthreads();   // all smem reads done before H reuse

    // store H = relu(acc + bias)
    {
        const float* bb1 = y ? bc1 : bo1;
        float* Hs = (float*)smem;
        #pragma unroll
        for (int ni = 0; ni < 8; ni++) {
            int colb = wn + ni * 8 + 2 * qd;
            float b0v = bb1[colb], b1v = bb1[colb + 1];
            #pragma unroll
            for (int mi = 0; mi < 4; mi++) {
                int r0 = wm + mi * 16 + g;
                Hs[r0 * HS + colb]           = fmaxf(acc[mi][ni][0] + b0v, 0.f);
                Hs[r0 * HS + colb + 1]       = fmaxf(acc[mi][ni][1] + b1v, 0.f);
                Hs[(r0 + 8) * HS + colb]     = fmaxf(acc[mi][ni][2] + b0v, 0.f);
                Hs[(r0 + 8) * HS + colb + 1] = fmaxf(acc[mi][ni][3] + b1v, 0.f);
            }
        }
    }
    __syncthreads();

    // heads + outputs (warp handles 16 rows)
    const float* Hs = (const float*)smem;
    if (y == 0) {
        for (int rr = 0; rr < 16; rr++) {
            int r = warp * 16 + rr;
            size_t qi = q0 + r;
            float ox = 0.f, oy = 0.f;
            for (int i = lane; i < BN; i += 32) {
                float h = Hs[r * HS + i];
                ox += h * Wo2[2 * i];
                oy += h * Wo2[2 * i + 1];
            }
            #pragma unroll
            for (int off = 16; off > 0; off >>= 1) {
                ox += __shfl_xor_sync(0xffffffffu, ox, off);
                oy += __shfl_xor_sync(0xffffffffu, oy, off);
            }
            float kx = 0.f, ky = 0.f;
            if (lane == 0) {
                ox += bo2[0]; oy += bo2[1];
                kx = IC[qi * 2 + 0] / (1.0f + expf(-ox));
                ky = IC[qi * 2 + 1] / (1.0f + expf(-oy));
            }
            kx = __shfl_sync(0xffffffffu, kx, 0);
            ky = __shfl_sync(0xffffffffu, ky, 0);
            for (int l = lane; l < 2 * NKPTS; l += 32)
                kp_out[qi * (2 * NKPTS) + l] = (l & 1) ? ky : kx;
        }
    } else {
        for (int rr = 0; rr < 16; rr++) {
            int r = warp * 16 + rr;
            size_t qi = q0 + r;
            float cl = 0.f;
            for (int i = lane; i < BN; i += 32)
                cl += Hs[r * HS + i] * Wc2[i];
            #pragma unroll
            for (int off = 16; off > 0; off >>= 1)
                cl += __shfl_xor_sync(0xffffffffu, cl, off);
            float cf = 0.f;
            if (lane == 0)
                cf = 1.0f / (1.0f + expf(-(cl + bc2[0])));
            cf = __shfl_sync(0xffffffffu, cf, 0);
            if (lane < NKPTS)
                conf_out[qi * NKPTS + lane] = cf;
        }
    }
}

extern "C" void kernel_launch(void* const* d_in, const int* in_sizes, int n_in,
                              void* d_out, int out_size) {
    const float* sf   = (const float*)d_in[0];
    const float* Q    = (const float*)d_in[2];
    const float* IC   = (const float*)d_in[3];
    const float* W1   = (const float*)d_in[4];
    const float* b1   = (const float*)d_in[5];
    const float* W2   = (const float*)d_in[6];
    const float* b2   = (const float*)d_in[7];
    const float* Wo1  = (const float*)d_in[8];
    const float* bo1  = (const float*)d_in[9];
    const float* Wo2  = (const float*)d_in[10];
    const float* bo2  = (const float*)d_in[11];
    const float* Wc1  = (const float*)d_in[12];
    const float* bc1  = (const float*)d_in[13];
    const float* Wc2  = (const float*)d_in[14];
    const float* bc2  = (const float*)d_in[15];
    const float* temp = (const float*)d_in[16];

    const int nq = in_sizes[2] / D;

    float* out       = (float*)d_out;
    float* kp_out    = out;
    float* conf_out  = kp_out   + (size_t)nq * 2 * NKPTS;
    float* dist_out  = conf_out + (size_t)nq * NKPTS;
    float* cls_out   = dist_out + (size_t)nq * NWAY * NKPTS;
    float* proto_out = cls_out  + (size_t)nq;

    convW<<<D, 512>>>(Wo1, Wc1);
    proto1<<<dim3(25, 8), PTPB>>>(sf, W1, b1);
    proto2<<<dim3(NWAY, 8), PTPB>>>(W2, b2, proto_out);

    preQ<<<nq / BM, PTPB>>>(Q, temp, dist_out, cls_out);

    cudaFuncSetAttribute((const void*)query_kernel,
                         cudaFuncAttributeMaxDynamicSharedMemorySize, SM_TOTAL);
    query_kernel<<<dim3(nq / BM, 2), TPB, SM_TOTAL>>>(
        IC, bo1, Wo2, bo2, bc1, Wc2, bc2, kp_out, conf_out);
}

// round 13
// speedup vs baseline: 1.4207x; 1.3803x over previous
#include <cuda_runtime.h>
#include <cuda_bf16.h>
#include <math.h>
#include <stdint.h>

#define D      512
#define NWAY   5
#define NKPTS  17
#define BM     128
#define BN     256
#define KC     64
#define NCH    8
#define TPB    256
#define PTPB   256
#define HS     260
#define NQTILES 512

// ---- GEMM smem (bf16 images) ----
#define SM_A      0                // 2 x 16384
#define SM_B      32768            // 2 x 32768
#define SM_TOTAL  135168           // covers H region (128*260*4 = 133120)

// ---- device scratch (allocation-free rule) ----
__device__ float   g_h1[25 * D];
__device__ float   g_proto[NWAY * D];
__device__ uint8_t g_W[2][NCH][32768];            // B: bf16 ldmatrix-block image
__device__ uint8_t g_Qimg[NQTILES][NCH][16384];   // A: bf16 ldmatrix-block image

// ---------------- helpers ----------------
__device__ __forceinline__ uint32_t smem_u32(const void* p) {
    uint32_t a;
    asm("{ .reg .u64 t; cvta.to.shared.u64 t, %1; cvt.u32.u64 %0, t; }" : "=r"(a) : "l"(p));
    return a;
}
__device__ __forceinline__ uint32_t pack_bf16x2(float lo, float hi) { // lo -> lower half
    uint32_t r; asm("cvt.rn.bf16x2.f32 %0, %1, %2;" : "=r"(r) : "f"(hi), "f"(lo)); return r;
}
__device__ __forceinline__ void cpa16(void* dst, const void* src) {
    uint32_t d = (uint32_t)__cvta_generic_to_shared(dst);
    asm volatile("cp.async.cg.shared.global [%0], [%1], 16;" :: "r"(d), "l"(src));
}
__device__ __forceinline__ void cp_commit() { asm volatile("cp.async.commit_group;"); }
__device__ __forceinline__ void cp_wait0()  { asm volatile("cp.async.wait_group 0;"); }

__device__ __forceinline__ void ldsm4(uint32_t* r, uint32_t addr) {
    asm volatile("ldmatrix.sync.aligned.m8n8.x4.shared.b16 {%0,%1,%2,%3}, [%4];"
        : "=r"(r[0]), "=r"(r[1]), "=r"(r[2]), "=r"(r[3]) : "r"(addr));
}
__device__ __forceinline__ void mma_bf16(float* d, const uint32_t* a, const uint32_t* b) {
    asm volatile("mma.sync.aligned.m16n8k16.row.col.f32.bf16.bf16.f32 "
        "{%0,%1,%2,%3},{%4,%5,%6,%7},{%8,%9},{%0,%1,%2,%3};"
        : "+f"(d[0]), "+f"(d[1]), "+f"(d[2]), "+f"(d[3])
        : "r"(a[0]), "r"(a[1]), "r"(a[2]), "r"(a[3]), "r"(b[0]), "r"(b[1]));
}

// ---------------- weight pre-convert (bf16 B image) ----------------
// Per (y, chunk): blk = ks16*64 + noct*2 + khalf, 128B = 8 n-rows x 16B (8 bf16 k).
__global__ void convW(const float* __restrict__ Wo1, const float* __restrict__ Wc1) {
    int k = blockIdx.x;           // 0..511
    int n = threadIdx.x;          // 0..511
    int y = n >> 8, nn = n & 255;
    float v = y ? Wc1[k * BN + nn] : Wo1[k * BN + nn];
    __nv_bfloat16 h = __float2bfloat16(v);
    int c = k >> 6, kc = k & 63;
    int ks = kc >> 4, kh = (kc >> 3) & 1, kpos = kc & 7;
    int noct = nn >> 3, r = nn & 7;
    uint32_t off = (uint32_t)(ks * 64 + noct * 2 + kh) * 128 + r * 16 + kpos * 2;
    *(__nv_bfloat16*)&g_W[y][c][off] = h;
}

// ---------------- prototype path ----------------
__global__ void proto1(const float* __restrict__ sf,
                       const float* __restrict__ W1,
                       const float* __restrict__ b1) {
    int s = blockIdx.x;
    int j = blockIdx.y * 64 + (threadIdx.x & 63);
    int kg = threadIdx.x >> 6;
    const float* srow = sf + s * D;
    float acc = 0.f;
    int k0 = kg * 128;
    #pragma unroll 8
    for (int k = k0; k < k0 + 128; k++)
        acc += srow[k] * W1[k * D + j];
    __shared__ float red[PTPB];
    red[threadIdx.x] = acc;
    __syncthreads();
    if (threadIdx.x < 64) {
        float v = red[threadIdx.x] + red[threadIdx.x + 64] + red[threadIdx.x + 128]
                + red[threadIdx.x + 192] + b1[j];
        g_h1[s * D + j] = fmaxf(v, 0.f);
    }
}

__global__ void proto2(const float* __restrict__ W2,
                       const float* __restrict__ b2,
                       float* __restrict__ proto_out) {
    int w = blockIdx.x;
    __shared__ float hsum[D];
    int t = threadIdx.x;
    for (int k = t; k < D; k += PTPB) {
        float a = 0.f;
        #pragma unroll
        for (int s = 0; s < 5; s++) a += g_h1[(w * 5 + s) * D + k];
        hsum[k] = a;
    }
    __syncthreads();
    int j = blockIdx.y * 64 + (t & 63);
    int kg = t >> 6;
    float acc = 0.f;
    int k0 = kg * 128;
    #pragma unroll 8
    for (int k = k0; k < k0 + 128; k++)
        acc += hsum[k] * W2[k * D + j];
    __shared__ float red[PTPB];
    red[t] = acc;
    __syncthreads();
    if (t < 64) {
        float p = (red[t] + red[t + 64] + red[t + 128] + red[t + 192]) * 0.2f + b2[j];
        g_proto[w * D + j] = p;
        #pragma unroll
        for (int kp = 0; kp < NKPTS; kp++)
            proto_out[(size_t)(w * NKPTS + kp) * D + j] = p;
    }
}

// ---------------- preQ: bf16 image transform + exact distances ----------------
__global__ void __launch_bounds__(PTPB, 2)
preQ(const float* __restrict__ Q, const float* __restrict__ temp,
     float* __restrict__ dist_out, float* __restrict__ cls_out) {
    __shared__ float sproto[NWAY * D];
    __shared__ float spn[NWAY];
    __shared__ float sdist[BM * NWAY];
    __shared__ float scls[BM];

    const int tid  = threadIdx.x;
    const int warp = tid >> 5;
    const int lane = tid & 31;
    const size_t q0 = (size_t)blockIdx.x * BM;

    for (int i = tid; i < NWAY * D; i += PTPB) sproto[i] = g_proto[i];
    __syncthreads();

    if (warp < NWAY) {
        float s = 0.f;
        for (int k = lane; k < D; k += 32) { float v = sproto[warp * D + k]; s += v * v; }
        #pragma unroll
        for (int off = 16; off > 0; off >>= 1) s += __shfl_xor_sync(0xffffffffu, s, off);
        if (lane == 0) spn[warp] = sqrtf(s);
    }
    __syncthreads();

    const int rsub = lane >> 2;    // row within warp octet
    const int lq   = lane & 3;     // k-quad group
    uint8_t* img = &g_Qimg[blockIdx.x][0][0];

    #pragma unroll 1
    for (int o = 0; o < 2; o++) {
        int rowl = o * 64 + warp * 8 + rsub;       // tile-local row 0..127
        const float* qr = Q + (q0 + rowl) * D;
        const int mblk = (rowl >> 4) * 4 + ((rowl >> 3) & 1);
        const int roff = (rowl & 7) * 16 + (lq & 1) * 8;
        const int khb  = (lq >> 1) * 2;            // k-half block offset

        float qq = 0.f, s0 = 0.f, s1 = 0.f, s2 = 0.f, s3 = 0.f, s4 = 0.f;
        #pragma unroll 8
        for (int j = 0; j < 32; j++) {
            float4 v = ((const float4*)qr)[lq + j * 4];
            int k = lq * 4 + j * 16;
            {
                float4 p0 = *(const float4*)(sproto + 0 * D + k);
                float4 p1 = *(const float4*)(sproto + 1 * D + k);
                float4 p2 = *(const float4*)(sproto + 2 * D + k);
                float4 p3 = *(const float4*)(sproto + 3 * D + k);
                float4 p4 = *(const float4*)(sproto + 4 * D + k);
                qq += v.x * v.x + v.y * v.y + v.z * v.z + v.w * v.w;
                s0 += v.x * p0.x + v.y * p0.y + v.z * p0.z + v.w * p0.w;
                s1 += v.x * p1.x + v.y * p1.y + v.z * p1.z + v.w * p1.w;
                s2 += v.x * p2.x + v.y * p2.y + v.z * p2.z + v.w * p2.w;
                s3 += v.x * p3.x + v.y * p3.y + v.z * p3.z + v.w * p3.w;
                s4 += v.x * p4.x + v.y * p4.y + v.z * p4.z + v.w * p4.w;
            }
            // bf16 image write: chunk c = j>>2, ks16 = j&3
            // blk = ks16*32 + khb + mblk; thread writes 8B (2 x bf16x2)
            int c = j >> 2;
            uint32_t off = (uint32_t)c * 16384u
                         + (uint32_t)((j & 3) * 32 + khb + mblk) * 128u + roff;
            *(uint2*)(img + off) =
                make_uint2(pack_bf16x2(v.x, v.y), pack_bf16x2(v.z, v.w));
        }

        // reduce over the 4-lane k-group
        #pragma unroll
        for (int off = 1; off <= 2; off <<= 1) {
            qq += __shfl_xor_sync(0xffffffffu, qq, off);
            s0 += __shfl_xor_sync(0xffffffffu, s0, off);
            s1 += __shfl_xor_sync(0xffffffffu, s1, off);
            s2 += __shfl_xor_sync(0xffffffffu, s2, off);
            s3 += __shfl_xor_sync(0xffffffffu, s3, off);
            s4 += __shfl_xor_sync(0xffffffffu, s4, off);
        }
        if (lq == 0) {
            const float T = *temp;
            float qn = sqrtf(qq);
            float sv[5] = {s0, s1, s2, s3, s4};
            float best = 3.402823e38f; int bi = 0;
            #pragma unroll
            for (int w = 0; w < NWAY; w++) {
                float denom = fmaxf(qn * spn[w], 1e-8f);
                float dv = (1.0f - sv[w] / denom) / T;
                sdist[rowl * NWAY + w] = dv;
                if (dv < best) { best = dv; bi = w; }
            }
            scls[rowl] = (float)bi;
        }
    }
    __syncthreads();

    // coalesced distance outputs (warp handles 16 rows)
    for (int rr = 0; rr < 16; rr++) {
        int r = warp * 16 + rr;
        size_t qi = q0 + r;
        for (int l = lane; l < NWAY * NKPTS; l += 32)
            dist_out[qi * (NWAY * NKPTS) + l] = sdist[r * NWAY + l / NKPTS];
        if (lane == 0) cls_out[qi] = scls[r];
    }
}

// ---------------- main GEMM kernel (bf16 m16n8k16, 64x64 warp tiles) ----------------
__global__ void __launch_bounds__(TPB, 1)
query_kernel(const float* __restrict__ IC,
             const float* __restrict__ bo1, const float* __restrict__ Wo2,
             const float* __restrict__ bo2,
             const float* __restrict__ bc1, const float* __restrict__ Wc2,
             const float* __restrict__ bc2,
             float* __restrict__ kp_out, float* __restrict__ conf_out) {
    extern __shared__ char smem[];
    const uint32_t sb = smem_u32(smem);

    const int tid  = threadIdx.x;
    const int warp = tid >> 5;
    const int lane = tid & 31;
    const int g    = lane >> 2;
    const int qd   = lane & 3;
    const int y    = blockIdx.y;
    const size_t q0 = (size_t)blockIdx.x * BM;

    const uint8_t* Asrc = &g_Qimg[blockIdx.x][0][0];

    auto cpA = [&](int c, int buf) {
        const uint8_t* src = Asrc + c * 16384;
        char* dst = smem + SM_A + buf * 16384;
        #pragma unroll
        for (int i = 0; i < 4; i++) {
            int idx = (tid + i * TPB) * 16;
            cpa16(dst + idx, src + idx);
        }
    };
    auto cpB = [&](int c, int buf) {
        const uint8_t* src = &g_W[y][c][0];
        char* dst = smem + SM_B + buf * 32768;
        #pragma unroll
        for (int i = 0; i < 8; i++) {
            int idx = (tid + i * TPB) * 16;
            cpa16(dst + idx, src + idx);
        }
    };

    cpA(0, 0);
    cpB(0, 0);
    cp_commit();
    cp_wait0();
    __syncthreads();

    float acc[4][8][4];
    #pragma unroll
    for (int mi = 0; mi < 4; mi++)
        #pragma unroll
        for (int ni = 0; ni < 8; ni++)
            #pragma unroll
            for (int i = 0; i < 4; i++) acc[mi][ni][i] = 0.f;

    const int wm = (warp & 1) * 64;            // 2 m-groups of 64
    const int wn = (warp >> 1) * 64;           // 4 n-groups of 64
    const uint32_t a_mt0 = (uint32_t)((warp & 1) * 4);
    const uint32_t b_blk0 = (uint32_t)(wn >> 2);

    #pragma unroll 1
    for (int c = 0; c < NCH; c++) {
        int buf = c & 1;
        if (c < NCH - 1) {
            cpA(c + 1, buf ^ 1);
            cpB(c + 1, buf ^ 1);
            cp_commit();
        }

        uint32_t ab   = sb + SM_A + buf * 16384;
        uint32_t bbuf = sb + SM_B + buf * 32768;
        #pragma unroll
        for (int ks = 0; ks < 4; ks++) {           // 4 k16 steps per 64-k chunk
            uint32_t Af[4][4];
            #pragma unroll
            for (int j = 0; j < 4; j++)
                ldsm4(Af[j], ab + (uint32_t)(ks * 32 + (a_mt0 + j) * 4) * 128 + lane * 16);
            #pragma unroll
            for (int p = 0; p < 4; p++) {
                uint32_t r[4];
                ldsm4(r, bbuf + (uint32_t)(ks * 64 + b_blk0 + 4 * p) * 128 + lane * 16);
                #pragma unroll
                for (int j = 0; j < 4; j++) {
                    mma_bf16(acc[j][2 * p],     Af[j], r);
                    mma_bf16(acc[j][2 * p + 1], Af[j], r + 2);
                }
            }
        }

        if (c < NCH - 1) {
            cp_wait0();
            __syncthreads();
        }
    }
    __syncthreads();   // all smem reads done before H reuse

    // store H = relu(acc + bias)
    {
        const float* bb1 = y ? bc1 : bo1;
        float* Hs = (float*)smem;
        #pragma unroll
        for (int ni = 0; ni < 8; ni++) {
            int colb = wn + ni * 8 + 2 * qd;
            float b0v = bb1[colb], b1v = bb1[colb + 1];
            #pragma unroll
            for (int mi = 0; mi < 4; mi++) {
                int r0 = wm + mi * 16 + g;
                Hs[r0 * HS + colb]           = fmaxf(acc[mi][ni][0] + b0v, 0.f);
                Hs[r0 * HS + colb + 1]       = fmaxf(acc[mi][ni][1] + b1v, 0.f);
                Hs[(r0 + 8) * HS + colb]     = fmaxf(acc[mi][ni][2] + b0v, 0.f);
                Hs[(r0 + 8) * HS + colb + 1] = fmaxf(acc[mi][ni][3] + b1v, 0.f);
            }
        }
    }
    __syncthreads();

    // heads + outputs (warp handles 16 rows)
    const float* Hs = (const float*)smem;
    if (y == 0) {
        for (int rr = 0; rr < 16; rr++) {
            int r = warp * 16 + rr;
            size_t qi = q0 + r;
            float ox = 0.f, oy = 0.f;
            for (int i = lane; i < BN; i += 32) {
                float h = Hs[r * HS + i];
                ox += h * Wo2[2 * i];
                oy += h * Wo2[2 * i + 1];
            }
            #pragma unroll
            for (int off = 16; off > 0; off >>= 1) {
                ox += __shfl_xor_sync(0xffffffffu, ox, off);
                oy += __shfl_xor_sync(0xffffffffu, oy, off);
            }
            float kx = 0.f, ky = 0.f;
            if (lane == 0) {
                ox += bo2[0]; oy += bo2[1];
                kx = IC[qi * 2 + 0] / (1.0f + expf(-ox));
                ky = IC[qi * 2 + 1] / (1.0f + expf(-oy));
            }
            kx = __shfl_sync(0xffffffffu, kx, 0);
            ky = __shfl_sync(0xffffffffu, ky, 0);
            for (int l = lane; l < 2 * NKPTS; l += 32)
                kp_out[qi * (2 * NKPTS) + l] = (l & 1) ? ky : kx;
        }
    } else {
        for (int rr = 0; rr < 16; rr++) {
            int r = warp * 16 + rr;
            size_t qi = q0 + r;
            float cl = 0.f;
            for (int i = lane; i < BN; i += 32)
                cl += Hs[r * HS + i] * Wc2[i];
            #pragma unroll
            for (int off = 16; off > 0; off >>= 1)
                cl += __shfl_xor_sync(0xffffffffu, cl, off);
            float cf = 0.f;
            if (lane == 0)
                cf = 1.0f / (1.0f + expf(-(cl + bc2[0])));
            cf = __shfl_sync(0xffffffffu, cf, 0);
            if (lane < NKPTS)
                conf_out[qi * NKPTS + lane] = cf;
        }
    }
}

extern "C" void kernel_launch(void* const* d_in, const int* in_sizes, int n_in,
                              void* d_out, int out_size) {
    const float* sf   = (const float*)d_in[0];
    const float* Q    = (const float*)d_in[2];
    const float* IC   = (const float*)d_in[3];
    const float* W1   = (const float*)d_in[4];
    const float* b1   = (const float*)d_in[5];
    const float* W2   = (const float*)d_in[6];
    const float* b2   = (const float*)d_in[7];
    const float* Wo1  = (const float*)d_in[8];
    const float* bo1  = (const float*)d_in[9];
    const float* Wo2  = (const float*)d_in[10];
    const float* bo2  = (const float*)d_in[11];
    const float* Wc1  = (const float*)d_in[12];
    const float* bc1  = (const float*)d_in[13];
    const float* Wc2  = (const float*)d_in[14];
    const float* bc2  = (const float*)d_in[15];
    const float* temp = (const float*)d_in[16];

    const int nq = in_sizes[2] / D;

    float* out       = (float*)d_out;
    float* kp_out    = out;
    float* conf_out  = kp_out   + (size_t)nq * 2 * NKPTS;
    float* dist_out  = conf_out + (size_t)nq * NKPTS;
    float* cls_out   = dist_out + (size_t)nq * NWAY * NKPTS;
    float* proto_out = cls_out  + (size_t)nq;

    convW<<<D, 512>>>(Wo1, Wc1);
    proto1<<<dim3(25, 8), PTPB>>>(sf, W1, b1);
    proto2<<<dim3(NWAY, 8), PTPB>>>(W2, b2, proto_out);

    preQ<<<nq / BM, PTPB>>>(Q, temp, dist_out, cls_out);

    cudaFuncSetAttribute((const void*)query_kernel,
                         cudaFuncAttributeMaxDynamicSharedMemorySize, SM_TOTAL);
    query_kernel<<<dim3(nq / BM, 2), TPB, SM_TOTAL>>>(
        IC, bo1, Wo2, bo2, bc1, Wc2, bc2, kp_out, conf_out);
}

// round 14
// speedup vs baseline: 1.5140x; 1.0656x over previous
#include <cuda_runtime.h>
#include <cuda_bf16.h>
#include <math.h>
#include <stdint.h>

#define D      512
#define NWAY   5
#define NKPTS  17
#define BM     128
#define BN     256
#define KC     64
#define NCH    8
#define TPB    512
#define PTPB   256
#define HS     260
#define NQTILES 512

// ---- GEMM smem (bf16 images) ----
#define SM_A      0                // 2 x 16384
#define SM_B      32768            // 2 x 32768
#define SM_TOTAL  135168           // covers H region (128*260*4 = 133120)

// ---- device scratch (allocation-free rule) ----
__device__ float   g_h1[25 * D];
__device__ float   g_proto[NWAY * D];
__device__ uint8_t g_W[2][NCH][32768];            // B: bf16 ldmatrix-block image
__device__ uint8_t g_Qimg[NQTILES][NCH][16384];   // A: bf16 ldmatrix-block image

// ---------------- helpers ----------------
__device__ __forceinline__ uint32_t smem_u32(const void* p) {
    uint32_t a;
    asm("{ .reg .u64 t; cvta.to.shared.u64 t, %1; cvt.u32.u64 %0, t; }" : "=r"(a) : "l"(p));
    return a;
}
__device__ __forceinline__ uint32_t pack_bf16x2(float lo, float hi) { // lo -> lower half
    uint32_t r; asm("cvt.rn.bf16x2.f32 %0, %1, %2;" : "=r"(r) : "f"(hi), "f"(lo)); return r;
}
__device__ __forceinline__ void cpa16(void* dst, const void* src) {
    uint32_t d = (uint32_t)__cvta_generic_to_shared(dst);
    asm volatile("cp.async.cg.shared.global [%0], [%1], 16;" :: "r"(d), "l"(src));
}
__device__ __forceinline__ void cp_commit() { asm volatile("cp.async.commit_group;"); }
__device__ __forceinline__ void cp_wait0()  { asm volatile("cp.async.wait_group 0;"); }

__device__ __forceinline__ void ldsm4(uint32_t* r, uint32_t addr) {
    asm volatile("ldmatrix.sync.aligned.m8n8.x4.shared.b16 {%0,%1,%2,%3}, [%4];"
        : "=r"(r[0]), "=r"(r[1]), "=r"(r[2]), "=r"(r[3]) : "r"(addr));
}
__device__ __forceinline__ void mma_bf16(float* d, const uint32_t* a, const uint32_t* b) {
    asm volatile("mma.sync.aligned.m16n8k16.row.col.f32.bf16.bf16.f32 "
        "{%0,%1,%2,%3},{%4,%5,%6,%7},{%8,%9},{%0,%1,%2,%3};"
        : "+f"(d[0]), "+f"(d[1]), "+f"(d[2]), "+f"(d[3])
        : "r"(a[0]), "r"(a[1]), "r"(a[2]), "r"(a[3]), "r"(b[0]), "r"(b[1]));
}

// ---------------- weight pre-convert (bf16 B image) ----------------
// Per (y, chunk): blk = ks16*64 + noct*2 + khalf, 128B = 8 n-rows x 16B (8 bf16 k).
__global__ void convW(const float* __restrict__ Wo1, const float* __restrict__ Wc1) {
    int k = blockIdx.x;           // 0..511
    int n = threadIdx.x;          // 0..511
    int y = n >> 8, nn = n & 255;
    float v = y ? Wc1[k * BN + nn] : Wo1[k * BN + nn];
    __nv_bfloat16 h = __float2bfloat16(v);
    int c = k >> 6, kc = k & 63;
    int ks = kc >> 4, kh = (kc >> 3) & 1, kpos = kc & 7;
    int noct = nn >> 3, r = nn & 7;
    uint32_t off = (uint32_t)(ks * 64 + noct * 2 + kh) * 128 + r * 16 + kpos * 2;
    *(__nv_bfloat16*)&g_W[y][c][off] = h;
}

// ---------------- prototype path ----------------
__global__ void proto1(const float* __restrict__ sf,
                       const float* __restrict__ W1,
                       const float* __restrict__ b1) {
    int s = blockIdx.x;
    int j = blockIdx.y * 64 + (threadIdx.x & 63);
    int kg = threadIdx.x >> 6;
    const float* srow = sf + s * D;
    float acc = 0.f;
    int k0 = kg * 128;
    #pragma unroll 8
    for (int k = k0; k < k0 + 128; k++)
        acc += srow[k] * W1[k * D + j];
    __shared__ float red[PTPB];
    red[threadIdx.x] = acc;
    __syncthreads();
    if (threadIdx.x < 64) {
        float v = red[threadIdx.x] + red[threadIdx.x + 64] + red[threadIdx.x + 128]
                + red[threadIdx.x + 192] + b1[j];
        g_h1[s * D + j] = fmaxf(v, 0.f);
    }
}

__global__ void proto2(const float* __restrict__ W2,
                       const float* __restrict__ b2,
                       float* __restrict__ proto_out) {
    int w = blockIdx.x;
    __shared__ float hsum[D];
    int t = threadIdx.x;
    for (int k = t; k < D; k += PTPB) {
        float a = 0.f;
        #pragma unroll
        for (int s = 0; s < 5; s++) a += g_h1[(w * 5 + s) * D + k];
        hsum[k] = a;
    }
    __syncthreads();
    int j = blockIdx.y * 64 + (t & 63);
    int kg = t >> 6;
    float acc = 0.f;
    int k0 = kg * 128;
    #pragma unroll 8
    for (int k = k0; k < k0 + 128; k++)
        acc += hsum[k] * W2[k * D + j];
    __shared__ float red[PTPB];
    red[t] = acc;
    __syncthreads();
    if (t < 64) {
        float p = (red[t] + red[t + 64] + red[t + 128] + red[t + 192]) * 0.2f + b2[j];
        g_proto[w * D + j] = p;
        #pragma unroll
        for (int kp = 0; kp < NKPTS; kp++)
            proto_out[(size_t)(w * NKPTS + kp) * D + j] = p;
    }
}

// ---------------- preQ: bf16 image transform + exact distances ----------------
__global__ void __launch_bounds__(PTPB, 2)
preQ(const float* __restrict__ Q, const float* __restrict__ temp,
     float* __restrict__ dist_out, float* __restrict__ cls_out) {
    __shared__ float sproto[NWAY * D];
    __shared__ float spn[NWAY];
    __shared__ float sdist[BM * NWAY];
    __shared__ float scls[BM];

    const int tid  = threadIdx.x;
    const int warp = tid >> 5;
    const int lane = tid & 31;
    const size_t q0 = (size_t)blockIdx.x * BM;

    for (int i = tid; i < NWAY * D; i += PTPB) sproto[i] = g_proto[i];
    __syncthreads();

    if (warp < NWAY) {
        float s = 0.f;
        for (int k = lane; k < D; k += 32) { float v = sproto[warp * D + k]; s += v * v; }
        #pragma unroll
        for (int off = 16; off > 0; off >>= 1) s += __shfl_xor_sync(0xffffffffu, s, off);
        if (lane == 0) spn[warp] = sqrtf(s);
    }
    __syncthreads();

    const int rsub = lane >> 2;    // row within warp octet
    const int lq   = lane & 3;     // k-quad group
    uint8_t* img = &g_Qimg[blockIdx.x][0][0];

    #pragma unroll 1
    for (int o = 0; o < 2; o++) {
        int rowl = o * 64 + warp * 8 + rsub;       // tile-local row 0..127
        const float* qr = Q + (q0 + rowl) * D;
        const int mblk = (rowl >> 4) * 4 + ((rowl >> 3) & 1);
        const int roff = (rowl & 7) * 16 + (lq & 1) * 8;
        const int khb  = (lq >> 1) * 2;            // k-half block offset

        float qq = 0.f, s0 = 0.f, s1 = 0.f, s2 = 0.f, s3 = 0.f, s4 = 0.f;
        #pragma unroll 8
        for (int j = 0; j < 32; j++) {
            float4 v = ((const float4*)qr)[lq + j * 4];
            int k = lq * 4 + j * 16;
            {
                float4 p0 = *(const float4*)(sproto + 0 * D + k);
                float4 p1 = *(const float4*)(sproto + 1 * D + k);
                float4 p2 = *(const float4*)(sproto + 2 * D + k);
                float4 p3 = *(const float4*)(sproto + 3 * D + k);
                float4 p4 = *(const float4*)(sproto + 4 * D + k);
                qq += v.x * v.x + v.y * v.y + v.z * v.z + v.w * v.w;
                s0 += v.x * p0.x + v.y * p0.y + v.z * p0.z + v.w * p0.w;
                s1 += v.x * p1.x + v.y * p1.y + v.z * p1.z + v.w * p1.w;
                s2 += v.x * p2.x + v.y * p2.y + v.z * p2.z + v.w * p2.w;
                s3 += v.x * p3.x + v.y * p3.y + v.z * p3.z + v.w * p3.w;
                s4 += v.x * p4.x + v.y * p4.y + v.z * p4.z + v.w * p4.w;
            }
            int c = j >> 2;
            uint32_t off = (uint32_t)c * 16384u
                         + (uint32_t)((j & 3) * 32 + khb + mblk) * 128u + roff;
            *(uint2*)(img + off) =
                make_uint2(pack_bf16x2(v.x, v.y), pack_bf16x2(v.z, v.w));
        }

        #pragma unroll
        for (int off = 1; off <= 2; off <<= 1) {
            qq += __shfl_xor_sync(0xffffffffu, qq, off);
            s0 += __shfl_xor_sync(0xffffffffu, s0, off);
            s1 += __shfl_xor_sync(0xffffffffu, s1, off);
            s2 += __shfl_xor_sync(0xffffffffu, s2, off);
            s3 += __shfl_xor_sync(0xffffffffu, s3, off);
            s4 += __shfl_xor_sync(0xffffffffu, s4, off);
        }
        if (lq == 0) {
            const float T = *temp;
            float qn = sqrtf(qq);
            float sv[5] = {s0, s1, s2, s3, s4};
            float best = 3.402823e38f; int bi = 0;
            #pragma unroll
            for (int w = 0; w < NWAY; w++) {
                float denom = fmaxf(qn * spn[w], 1e-8f);
                float dv = (1.0f - sv[w] / denom) / T;
                sdist[rowl * NWAY + w] = dv;
                if (dv < best) { best = dv; bi = w; }
            }
            scls[rowl] = (float)bi;
        }
    }
    __syncthreads();

    for (int rr = 0; rr < 16; rr++) {
        int r = warp * 16 + rr;
        size_t qi = q0 + r;
        for (int l = lane; l < NWAY * NKPTS; l += 32)
            dist_out[qi * (NWAY * NKPTS) + l] = sdist[r * NWAY + l / NKPTS];
        if (lane == 0) cls_out[qi] = scls[r];
    }
}

// ---------------- main GEMM kernel (bf16, TPB=512, 64x32 warp tiles) ----------------
__global__ void __launch_bounds__(TPB, 1)
query_kernel(const float* __restrict__ IC,
             const float* __restrict__ bo1, const float* __restrict__ Wo2,
             const float* __restrict__ bo2,
             const float* __restrict__ bc1, const float* __restrict__ Wc2,
             const float* __restrict__ bc2,
             float* __restrict__ kp_out, float* __restrict__ conf_out) {
    extern __shared__ char smem[];
    const uint32_t sb = smem_u32(smem);

    const int tid  = threadIdx.x;
    const int warp = tid >> 5;
    const int lane = tid & 31;
    const int g    = lane >> 2;
    const int qd   = lane & 3;
    const int y    = blockIdx.y;
    const size_t q0 = (size_t)blockIdx.x * BM;

    const uint8_t* Asrc = &g_Qimg[blockIdx.x][0][0];

    auto cpA = [&](int c, int buf) {
        const uint8_t* src = Asrc + c * 16384;
        char* dst = smem + SM_A + buf * 16384;
        #pragma unroll
        for (int i = 0; i < 2; i++) {
            int idx = (tid + i * TPB) * 16;
            cpa16(dst + idx, src + idx);
        }
    };
    auto cpB = [&](int c, int buf) {
        const uint8_t* src = &g_W[y][c][0];
        char* dst = smem + SM_B + buf * 32768;
        #pragma unroll
        for (int i = 0; i < 4; i++) {
            int idx = (tid + i * TPB) * 16;
            cpa16(dst + idx, src + idx);
        }
    };

    cpA(0, 0);
    cpB(0, 0);
    cp_commit();
    cp_wait0();
    __syncthreads();

    float acc[4][4][4];
    #pragma unroll
    for (int mi = 0; mi < 4; mi++)
        #pragma unroll
        for (int ni = 0; ni < 4; ni++)
            #pragma unroll
            for (int i = 0; i < 4; i++) acc[mi][ni][i] = 0.f;

    const int wm = (warp & 1) * 64;            // 2 m-groups of 64
    const int wn = (warp >> 1) * 32;           // 8 n-groups of 32
    const uint32_t a_mt0 = (uint32_t)((warp & 1) * 4);
    const uint32_t b_blk0 = (uint32_t)(wn >> 2);

    #pragma unroll 1
    for (int c = 0; c < NCH; c++) {
        int buf = c & 1;
        if (c < NCH - 1) {
            cpA(c + 1, buf ^ 1);
            cpB(c + 1, buf ^ 1);
            cp_commit();
        }

        uint32_t ab   = sb + SM_A + buf * 16384;
        uint32_t bbuf = sb + SM_B + buf * 32768;
        #pragma unroll
        for (int ks = 0; ks < 4; ks++) {           // 4 k16 steps per 64-k chunk
            uint32_t Af[4][4];
            #pragma unroll
            for (int j = 0; j < 4; j++)
                ldsm4(Af[j], ab + (uint32_t)(ks * 32 + (a_mt0 + j) * 4) * 128 + lane * 16);
            #pragma unroll
            for (int p = 0; p < 2; p++) {
                uint32_t r[4];
                ldsm4(r, bbuf + (uint32_t)(ks * 64 + b_blk0 + 4 * p) * 128 + lane * 16);
                #pragma unroll
                for (int j = 0; j < 4; j++) {
                    mma_bf16(acc[j][2 * p],     Af[j], r);
                    mma_bf16(acc[j][2 * p + 1], Af[j], r + 2);
                }
            }
        }

        if (c < NCH - 1) {
            cp_wait0();
            __syncthreads();
        }
    }
    __syncthreads();   // all smem reads done before H reuse

    // store H = relu(acc + bias)
    {
        const float* bb1 = y ? bc1 : bo1;
        float* Hs = (float*)smem;
        #pragma unroll
        for (int ni = 0; ni < 4; ni++) {
            int colb = wn + ni * 8 + 2 * qd;
            float b0v = bb1[colb], b1v = bb1[colb + 1];
            #pragma unroll
            for (int mi = 0; mi < 4; mi++) {
                int r0 = wm + mi * 16 + g;
                Hs[r0 * HS + colb]           = fmaxf(acc[mi][ni][0] + b0v, 0.f);
                Hs[r0 * HS + colb + 1]       = fmaxf(acc[mi][ni][1] + b1v, 0.f);
                Hs[(r0 + 8) * HS + colb]     = fmaxf(acc[mi][ni][2] + b0v, 0.f);
                Hs[(r0 + 8) * HS + colb + 1] = fmaxf(acc[mi][ni][3] + b1v, 0.f);
            }
        }
    }
    __syncthreads();

    // heads + outputs (warp handles 8 rows)
    const float* Hs = (const float*)smem;
    if (y == 0) {
        for (int rr = 0; rr < 8; rr++) {
            int r = warp * 8 + rr;
            size_t qi = q0 + r;
            float ox = 0.f, oy = 0.f;
            for (int i = lane; i < BN; i += 32) {
                float h = Hs[r * HS + i];
                ox += h * Wo2[2 * i];
                oy += h * Wo2[2 * i + 1];
            }
            #pragma unroll
            for (int off = 16; off > 0; off >>= 1) {
                ox += __shfl_xor_sync(0xffffffffu, ox, off);
                oy += __shfl_xor_sync(0xffffffffu, oy, off);
            }
            float kx = 0.f, ky = 0.f;
            if (lane == 0) {
                ox += bo2[0]; oy += bo2[1];
                kx = IC[qi * 2 + 0] / (1.0f + expf(-ox));
                ky = IC[qi * 2 + 1] / (1.0f + expf(-oy));
            }
            kx = __shfl_sync(0xffffffffu, kx, 0);
            ky = __shfl_sync(0xffffffffu, ky, 0);
            for (int l = lane; l < 2 * NKPTS; l += 32)
                kp_out[qi * (2 * NKPTS) + l] = (l & 1) ? ky : kx;
        }
    } else {
        for (int rr = 0; rr < 8; rr++) {
            int r = warp * 8 + rr;
            size_t qi = q0 + r;
            float cl = 0.f;
            for (int i = lane; i < BN; i += 32)
                cl += Hs[r * HS + i] * Wc2[i];
            #pragma unroll
            for (int off = 16; off > 0; off >>= 1)
                cl += __shfl_xor_sync(0xffffffffu, cl, off);
            float cf = 0.f;
            if (lane == 0)
                cf = 1.0f / (1.0f + expf(-(cl + bc2[0])));
            cf = __shfl_sync(0xffffffffu, cf, 0);
            if (lane < NKPTS)
                conf_out[qi * NKPTS + lane] = cf;
        }
    }
}

extern "C" void kernel_launch(void* const* d_in, const int* in_sizes, int n_in,
                              void* d_out, int out_size) {
    const float* sf   = (const float*)d_in[0];
    const float* Q    = (const float*)d_in[2];
    const float* IC   = (const float*)d_in[3];
    const float* W1   = (const float*)d_in[4];
    const float* b1   = (const float*)d_in[5];
    const float* W2   = (const float*)d_in[6];
    const float* b2   = (const float*)d_in[7];
    const float* Wo1  = (const float*)d_in[8];
    const float* bo1  = (const float*)d_in[9];
    const float* Wo2  = (const float*)d_in[10];
    const float* bo2  = (const float*)d_in[11];
    const float* Wc1  = (const float*)d_in[12];
    const float* bc1  = (const float*)d_in[13];
    const float* Wc2  = (const float*)d_in[14];
    const float* bc2  = (const float*)d_in[15];
    const float* temp = (const float*)d_in[16];

    const int nq = in_sizes[2] / D;

    float* out       = (float*)d_out;
    float* kp_out    = out;
    float* conf_out  = kp_out   + (size_t)nq * 2 * NKPTS;
    float* dist_out  = conf_out + (size_t)nq * NKPTS;
    float* cls_out   = dist_out + (size_t)nq * NWAY * NKPTS;
    float* proto_out = cls_out  + (size_t)nq;

    convW<<<D, 512>>>(Wo1, Wc1);
    proto1<<<dim3(25, 8), PTPB>>>(sf, W1, b1);
    proto2<<<dim3(NWAY, 8), PTPB>>>(W2, b2, proto_out);

    preQ<<<nq / BM, PTPB>>>(Q, temp, dist_out, cls_out);

    cudaFuncSetAttribute((const void*)query_kernel,
                         cudaFuncAttributeMaxDynamicSharedMemorySize, SM_TOTAL);
    query_kernel<<<dim3(nq / BM, 2), TPB, SM_TOTAL>>>(
        IC, bo1, Wo2, bo2, bc1, Wc2, bc2, kp_out, conf_out);
}

// round 15
// speedup vs baseline: 1.5966x; 1.0545x over previous
#include <cuda_runtime.h>
#include <cuda_bf16.h>
#include <math.h>
#include <stdint.h>

#define D      512
#define NWAY   5
#define NKPTS  17
#define BMP    128          // preQ tile rows (image granule)
#define BM     64           // GEMM tile rows (half-image)
#define BN     256
#define KC     64
#define NCH    8
#define TPB    256
#define PTPB   256
#define HS     260
#define NQTILES 512

// ---- GEMM smem (bf16 images) ----
#define SM_A      0                // 2 x 8192
#define SM_B      16384            // 2 x 32768
#define SM_TOTAL  81920            // H region 64*260*4 = 66560 fits

// ---- device scratch (allocation-free rule) ----
__device__ float   g_h1[25 * D];
__device__ float   g_proto[NWAY * D];
__device__ uint8_t g_W[2][NCH][32768];            // B: bf16 ldmatrix-block image
__device__ uint8_t g_Qimg[NQTILES][NCH][16384];   // A: bf16 ldmatrix-block image (128-row tiles)

// ---------------- helpers ----------------
__device__ __forceinline__ uint32_t smem_u32(const void* p) {
    uint32_t a;
    asm("{ .reg .u64 t; cvta.to.shared.u64 t, %1; cvt.u32.u64 %0, t; }" : "=r"(a) : "l"(p));
    return a;
}
__device__ __forceinline__ uint32_t pack_bf16x2(float lo, float hi) { // lo -> lower half
    uint32_t r; asm("cvt.rn.bf16x2.f32 %0, %1, %2;" : "=r"(r) : "f"(hi), "f"(lo)); return r;
}
__device__ __forceinline__ void cpa16(void* dst, const void* src) {
    uint32_t d = (uint32_t)__cvta_generic_to_shared(dst);
    asm volatile("cp.async.cg.shared.global [%0], [%1], 16;" :: "r"(d), "l"(src));
}
__device__ __forceinline__ void cp_commit() { asm volatile("cp.async.commit_group;"); }
__device__ __forceinline__ void cp_wait0()  { asm volatile("cp.async.wait_group 0;"); }

__device__ __forceinline__ void ldsm4(uint32_t* r, uint32_t addr) {
    asm volatile("ldmatrix.sync.aligned.m8n8.x4.shared.b16 {%0,%1,%2,%3}, [%4];"
        : "=r"(r[0]), "=r"(r[1]), "=r"(r[2]), "=r"(r[3]) : "r"(addr));
}
__device__ __forceinline__ void mma_bf16(float* d, const uint32_t* a, const uint32_t* b) {
    asm volatile("mma.sync.aligned.m16n8k16.row.col.f32.bf16.bf16.f32 "
        "{%0,%1,%2,%3},{%4,%5,%6,%7},{%8,%9},{%0,%1,%2,%3};"
        : "+f"(d[0]), "+f"(d[1]), "+f"(d[2]), "+f"(d[3])
        : "r"(a[0]), "r"(a[1]), "r"(a[2]), "r"(a[3]), "r"(b[0]), "r"(b[1]));
}

// ---------------- weight pre-convert (bf16 B image) ----------------
__global__ void convW(const float* __restrict__ Wo1, const float* __restrict__ Wc1) {
    int k = blockIdx.x;           // 0..511
    int n = threadIdx.x;          // 0..511
    int y = n >> 8, nn = n & 255;
    float v = y ? Wc1[k * BN + nn] : Wo1[k * BN + nn];
    __nv_bfloat16 h = __float2bfloat16(v);
    int c = k >> 6, kc = k & 63;
    int ks = kc >> 4, kh = (kc >> 3) & 1, kpos = kc & 7;
    int noct = nn >> 3, r = nn & 7;
    uint32_t off = (uint32_t)(ks * 64 + noct * 2 + kh) * 128 + r * 16 + kpos * 2;
    *(__nv_bfloat16*)&g_W[y][c][off] = h;
}

// ---------------- prototype path ----------------
__global__ void proto1(const float* __restrict__ sf,
                       const float* __restrict__ W1,
                       const float* __restrict__ b1) {
    int s = blockIdx.x;
    int j = blockIdx.y * 64 + (threadIdx.x & 63);
    int kg = threadIdx.x >> 6;
    const float* srow = sf + s * D;
    float acc = 0.f;
    int k0 = kg * 128;
    #pragma unroll 8
    for (int k = k0; k < k0 + 128; k++)
        acc += srow[k] * W1[k * D + j];
    __shared__ float red[PTPB];
    red[threadIdx.x] = acc;
    __syncthreads();
    if (threadIdx.x < 64) {
        float v = red[threadIdx.x] + red[threadIdx.x + 64] + red[threadIdx.x + 128]
                + red[threadIdx.x + 192] + b1[j];
        g_h1[s * D + j] = fmaxf(v, 0.f);
    }
}

__global__ void proto2(const float* __restrict__ W2,
                       const float* __restrict__ b2,
                       float* __restrict__ proto_out) {
    int w = blockIdx.x;
    __shared__ float hsum[D];
    int t = threadIdx.x;
    for (int k = t; k < D; k += PTPB) {
        float a = 0.f;
        #pragma unroll
        for (int s = 0; s < 5; s++) a += g_h1[(w * 5 + s) * D + k];
        hsum[k] = a;
    }
    __syncthreads();
    int j = blockIdx.y * 64 + (t & 63);
    int kg = t >> 6;
    float acc = 0.f;
    int k0 = kg * 128;
    #pragma unroll 8
    for (int k = k0; k < k0 + 128; k++)
        acc += hsum[k] * W2[k * D + j];
    __shared__ float red[PTPB];
    red[t] = acc;
    __syncthreads();
    if (t < 64) {
        float p = (red[t] + red[t + 64] + red[t + 128] + red[t + 192]) * 0.2f + b2[j];
        g_proto[w * D + j] = p;
        #pragma unroll
        for (int kp = 0; kp < NKPTS; kp++)
            proto_out[(size_t)(w * NKPTS + kp) * D + j] = p;
    }
}

// ---------------- preQ: bf16 image transform + exact distances (128-row tiles) ----------------
__global__ void __launch_bounds__(PTPB, 2)
preQ(const float* __restrict__ Q, const float* __restrict__ temp,
     float* __restrict__ dist_out, float* __restrict__ cls_out) {
    __shared__ float sproto[NWAY * D];
    __shared__ float spn[NWAY];
    __shared__ float sdist[BMP * NWAY];
    __shared__ float scls[BMP];

    const int tid  = threadIdx.x;
    const int warp = tid >> 5;
    const int lane = tid & 31;
    const size_t q0 = (size_t)blockIdx.x * BMP;

    for (int i = tid; i < NWAY * D; i += PTPB) sproto[i] = g_proto[i];
    __syncthreads();

    if (warp < NWAY) {
        float s = 0.f;
        for (int k = lane; k < D; k += 32) { float v = sproto[warp * D + k]; s += v * v; }
        #pragma unroll
        for (int off = 16; off > 0; off >>= 1) s += __shfl_xor_sync(0xffffffffu, s, off);
        if (lane == 0) spn[warp] = sqrtf(s);
    }
    __syncthreads();

    const int rsub = lane >> 2;    // row within warp octet
    const int lq   = lane & 3;     // k-quad group
    uint8_t* img = &g_Qimg[blockIdx.x][0][0];

    #pragma unroll 1
    for (int o = 0; o < 2; o++) {
        int rowl = o * 64 + warp * 8 + rsub;       // tile-local row 0..127
        const float* qr = Q + (q0 + rowl) * D;
        const int mblk = (rowl >> 4) * 4 + ((rowl >> 3) & 1);
        const int roff = (rowl & 7) * 16 + (lq & 1) * 8;
        const int khb  = (lq >> 1) * 2;            // k-half block offset

        float qq = 0.f, s0 = 0.f, s1 = 0.f, s2 = 0.f, s3 = 0.f, s4 = 0.f;
        #pragma unroll 8
        for (int j = 0; j < 32; j++) {
            float4 v = ((const float4*)qr)[lq + j * 4];
            int k = lq * 4 + j * 16;
            {
                float4 p0 = *(const float4*)(sproto + 0 * D + k);
                float4 p1 = *(const float4*)(sproto + 1 * D + k);
                float4 p2 = *(const float4*)(sproto + 2 * D + k);
                float4 p3 = *(const float4*)(sproto + 3 * D + k);
                float4 p4 = *(const float4*)(sproto + 4 * D + k);
                qq += v.x * v.x + v.y * v.y + v.z * v.z + v.w * v.w;
                s0 += v.x * p0.x + v.y * p0.y + v.z * p0.z + v.w * p0.w;
                s1 += v.x * p1.x + v.y * p1.y + v.z * p1.z + v.w * p1.w;
                s2 += v.x * p2.x + v.y * p2.y + v.z * p2.z + v.w * p2.w;
                s3 += v.x * p3.x + v.y * p3.y + v.z * p3.z + v.w * p3.w;
                s4 += v.x * p4.x + v.y * p4.y + v.z * p4.z + v.w * p4.w;
            }
            int c = j >> 2;
            uint32_t off = (uint32_t)c * 16384u
                         + (uint32_t)((j & 3) * 32 + khb + mblk) * 128u + roff;
            *(uint2*)(img + off) =
                make_uint2(pack_bf16x2(v.x, v.y), pack_bf16x2(v.z, v.w));
        }

        #pragma unroll
        for (int off = 1; off <= 2; off <<= 1) {
            qq += __shfl_xor_sync(0xffffffffu, qq, off);
            s0 += __shfl_xor_sync(0xffffffffu, s0, off);
            s1 += __shfl_xor_sync(0xffffffffu, s1, off);
            s2 += __shfl_xor_sync(0xffffffffu, s2, off);
            s3 += __shfl_xor_sync(0xffffffffu, s3, off);
            s4 += __shfl_xor_sync(0xffffffffu, s4, off);
        }
        if (lq == 0) {
            const float T = *temp;
            float qn = sqrtf(qq);
            float sv[5] = {s0, s1, s2, s3, s4};
            float best = 3.402823e38f; int bi = 0;
            #pragma unroll
            for (int w = 0; w < NWAY; w++) {
                float denom = fmaxf(qn * spn[w], 1e-8f);
                float dv = (1.0f - sv[w] / denom) / T;
                sdist[rowl * NWAY + w] = dv;
                if (dv < best) { best = dv; bi = w; }
            }
            scls[rowl] = (float)bi;
        }
    }
    __syncthreads();

    for (int rr = 0; rr < 16; rr++) {
        int r = warp * 16 + rr;
        size_t qi = q0 + r;
        for (int l = lane; l < NWAY * NKPTS; l += 32)
            dist_out[qi * (NWAY * NKPTS) + l] = sdist[r * NWAY + l / NKPTS];
        if (lane == 0) cls_out[qi] = scls[r];
    }
}

// ---------------- main GEMM kernel (BM=64, 2 CTAs/SM, 32x64 warp tiles) ----------------
__global__ void __launch_bounds__(TPB, 2)
query_kernel(const float* __restrict__ IC,
             const float* __restrict__ bo1, const float* __restrict__ Wo2,
             const float* __restrict__ bo2,
             const float* __restrict__ bc1, const float* __restrict__ Wc2,
             const float* __restrict__ bc2,
             float* __restrict__ kp_out, float* __restrict__ conf_out) {
    extern __shared__ char smem[];
    const uint32_t sb = smem_u32(smem);

    const int tid  = threadIdx.x;
    const int warp = tid >> 5;
    const int lane = tid & 31;
    const int g    = lane >> 2;
    const int qd   = lane & 3;
    const int y    = blockIdx.y;
    const int ht   = blockIdx.x;       // half-tile index
    const int tile = ht >> 1;
    const int half = ht & 1;
    const size_t q0 = (size_t)ht * BM;

    const uint8_t* Asrc = &g_Qimg[tile][0][0];

    // A half-image: per ks, the 16 blocks [ks*32 + half*16, +16) = contiguous 2KB
    auto cpA = [&](int c, int buf) {
        const uint8_t* src = Asrc + c * 16384;
        char* dst = smem + SM_A + buf * 8192;
        #pragma unroll
        for (int i = 0; i < 2; i++) {
            int idx = tid + i * TPB;           // 0..511
            int run = idx >> 7, w = idx & 127;
            cpa16(dst + run * 2048 + w * 16,
                  src + (uint32_t)(run * 32 + half * 16) * 128 + w * 16);
        }
    };
    auto cpB = [&](int c, int buf) {
        const uint8_t* src = &g_W[y][c][0];
        char* dst = smem + SM_B + buf * 32768;
        #pragma unroll
        for (int i = 0; i < 8; i++) {
            int idx = (tid + i * TPB) * 16;
            cpa16(dst + idx, src + idx);
        }
    };

    cpA(0, 0);
    cpB(0, 0);
    cp_commit();
    cp_wait0();
    __syncthreads();

    float acc[2][8][4];
    #pragma unroll
    for (int mi = 0; mi < 2; mi++)
        #pragma unroll
        for (int ni = 0; ni < 8; ni++)
            #pragma unroll
            for (int i = 0; i < 4; i++) acc[mi][ni][i] = 0.f;

    const int wm = (warp & 1) * 32;            // 2 m-groups of 32
    const int wn = (warp >> 1) * 64;           // 4 n-groups of 64
    const uint32_t a_mt0 = (uint32_t)((warp & 1) * 2);
    const uint32_t b_blk0 = (uint32_t)(wn >> 2);

    #pragma unroll 1
    for (int c = 0; c < NCH; c++) {
        int buf = c & 1;
        if (c < NCH - 1) {
            cpA(c + 1, buf ^ 1);
            cpB(c + 1, buf ^ 1);
            cp_commit();
        }

        uint32_t ab   = sb + SM_A + buf * 8192;
        uint32_t bbuf = sb + SM_B + buf * 32768;
        #pragma unroll
        for (int ks = 0; ks < 4; ks++) {           // 4 k16 steps per 64-k chunk
            uint32_t Af[2][4];
            #pragma unroll
            for (int j = 0; j < 2; j++)
                ldsm4(Af[j], ab + (uint32_t)(ks * 16 + (a_mt0 + j) * 4) * 128 + lane * 16);
            #pragma unroll
            for (int p = 0; p < 4; p++) {
                uint32_t r[4];
                ldsm4(r, bbuf + (uint32_t)(ks * 64 + b_blk0 + 4 * p) * 128 + lane * 16);
                #pragma unroll
                for (int j = 0; j < 2; j++) {
                    mma_bf16(acc[j][2 * p],     Af[j], r);
                    mma_bf16(acc[j][2 * p + 1], Af[j], r + 2);
                }
            }
        }

        if (c < NCH - 1) {
            cp_wait0();
            __syncthreads();
        }
    }
    __syncthreads();   // all smem reads done before H reuse

    // store H = relu(acc + bias)  (64 rows x 256 cols)
    {
        const float* bb1 = y ? bc1 : bo1;
        float* Hs = (float*)smem;
        #pragma unroll
        for (int ni = 0; ni < 8; ni++) {
            int colb = wn + ni * 8 + 2 * qd;
            float b0v = bb1[colb], b1v = bb1[colb + 1];
            #pragma unroll
            for (int mi = 0; mi < 2; mi++) {
                int r0 = wm + mi * 16 + g;
                Hs[r0 * HS + colb]           = fmaxf(acc[mi][ni][0] + b0v, 0.f);
                Hs[r0 * HS + colb + 1]       = fmaxf(acc[mi][ni][1] + b1v, 0.f);
                Hs[(r0 + 8) * HS + colb]     = fmaxf(acc[mi][ni][2] + b0v, 0.f);
                Hs[(r0 + 8) * HS + colb + 1] = fmaxf(acc[mi][ni][3] + b1v, 0.f);
            }
        }
    }
    __syncthreads();

    // heads + outputs (warp handles 8 rows)
    const float* Hs = (const float*)smem;
    if (y == 0) {
        for (int rr = 0; rr < 8; rr++) {
            int r = warp * 8 + rr;
            size_t qi = q0 + r;
            float ox = 0.f, oy = 0.f;
            for (int i = lane; i < BN; i += 32) {
                float h = Hs[r * HS + i];
                ox += h * Wo2[2 * i];
                oy += h * Wo2[2 * i + 1];
            }
            #pragma unroll
            for (int off = 16; off > 0; off >>= 1) {
                ox += __shfl_xor_sync(0xffffffffu, ox, off);
                oy += __shfl_xor_sync(0xffffffffu, oy, off);
            }
            float kx = 0.f, ky = 0.f;
            if (lane == 0) {
                ox += bo2[0]; oy += bo2[1];
                kx = IC[qi * 2 + 0] / (1.0f + expf(-ox));
                ky = IC[qi * 2 + 1] / (1.0f + expf(-oy));
            }
            kx = __shfl_sync(0xffffffffu, kx, 0);
            ky = __shfl_sync(0xffffffffu, ky, 0);
            for (int l = lane; l < 2 * NKPTS; l += 32)
                kp_out[qi * (2 * NKPTS) + l] = (l & 1) ? ky : kx;
        }
    } else {
        for (int rr = 0; rr < 8; rr++) {
            int r = warp * 8 + rr;
            size_t qi = q0 + r;
            float cl = 0.f;
            for (int i = lane; i < BN; i += 32)
                cl += Hs[r * HS + i] * Wc2[i];
            #pragma unroll
            for (int off = 16; off > 0; off >>= 1)
                cl += __shfl_xor_sync(0xffffffffu, cl, off);
            float cf = 0.f;
            if (lane == 0)
                cf = 1.0f / (1.0f + expf(-(cl + bc2[0])));
            cf = __shfl_sync(0xffffffffu, cf, 0);
            if (lane < NKPTS)
                conf_out[qi * NKPTS + lane] = cf;
        }
    }
}

extern "C" void kernel_launch(void* const* d_in, const int* in_sizes, int n_in,
                              void* d_out, int out_size) {
    const float* sf   = (const float*)d_in[0];
    const float* Q    = (const float*)d_in[2];
    const float* IC   = (const float*)d_in[3];
    const float* W1   = (const float*)d_in[4];
    const float* b1   = (const float*)d_in[5];
    const float* W2   = (const float*)d_in[6];
    const float* b2   = (const float*)d_in[7];
    const float* Wo1  = (const float*)d_in[8];
    const float* bo1  = (const float*)d_in[9];
    const float* Wo2  = (const float*)d_in[10];
    const float* bo2  = (const float*)d_in[11];
    const float* Wc1  = (const float*)d_in[12];
    const float* bc1  = (const float*)d_in[13];
    const float* Wc2  = (const float*)d_in[14];
    const float* bc2  = (const float*)d_in[15];
    const float* temp = (const float*)d_in[16];

    const int nq = in_sizes[2] / D;

    float* out       = (float*)d_out;
    float* kp_out    = out;
    float* conf_out  = kp_out   + (size_t)nq * 2 * NKPTS;
    float* dist_out  = conf_out + (size_t)nq * NKPTS;
    float* cls_out   = dist_out + (size_t)nq * NWAY * NKPTS;
    float* proto_out = cls_out  + (size_t)nq;

    convW<<<D, 512>>>(Wo1, Wc1);
    proto1<<<dim3(25, 8), PTPB>>>(sf, W1, b1);
    proto2<<<dim3(NWAY, 8), PTPB>>>(W2, b2, proto_out);

    preQ<<<nq / BMP, PTPB>>>(Q, temp, dist_out, cls_out);

    cudaFuncSetAttribute((const void*)query_kernel,
                         cudaFuncAttributeMaxDynamicSharedMemorySize, SM_TOTAL);
    query_kernel<<<dim3(nq / BM, 2), TPB, SM_TOTAL>>>(
        IC, bo1, Wo2, bo2, bc1, Wc2, bc2, kp_out, conf_out);
}

// round 16
// speedup vs baseline: 1.7770x; 1.1130x over previous
#include <cuda_runtime.h>
#include <cuda_bf16.h>
#include <math.h>
#include <stdint.h>

#define D      512
#define NWAY   5
#define NKPTS  17
#define BMP    128          // preQ tile rows (image granule)
#define BM     64           // GEMM tile rows (half-image)
#define BN     256
#define KC     64
#define NCH    8
#define TPB    256
#define PTPB   256
#define NQTILES 512

// ---- GEMM smem ----
#define SM_A      0                // 2 x 8192
#define SM_B      16384            // 2 x 32768 -> ends 81920
#define SM_BIAS   81920            // 256 f
#define SM_W2     82944            // 512 f
#define SM_PART   84992            // 64*4 float2 = 2048
#define SM_RES    87040            // 128 f
#define SM_TOTAL  87552

// ---- device scratch (allocation-free rule) ----
__device__ float   g_h1[25 * D];
__device__ float   g_proto[NWAY * D];
__device__ uint8_t g_W[2][NCH][32768];            // B: bf16 ldmatrix-block image
__device__ uint8_t g_Qimg[NQTILES][NCH][16384];   // A: bf16 ldmatrix-block image

// ---------------- helpers ----------------
__device__ __forceinline__ uint32_t smem_u32(const void* p) {
    uint32_t a;
    asm("{ .reg .u64 t; cvta.to.shared.u64 t, %1; cvt.u32.u64 %0, t; }" : "=r"(a) : "l"(p));
    return a;
}
__device__ __forceinline__ uint32_t pack_bf16x2(float lo, float hi) {
    uint32_t r; asm("cvt.rn.bf16x2.f32 %0, %1, %2;" : "=r"(r) : "f"(hi), "f"(lo)); return r;
}
__device__ __forceinline__ void cpa16(void* dst, const void* src) {
    uint32_t d = (uint32_t)__cvta_generic_to_shared(dst);
    asm volatile("cp.async.cg.shared.global [%0], [%1], 16;" :: "r"(d), "l"(src));
}
__device__ __forceinline__ void cp_commit() { asm volatile("cp.async.commit_group;"); }
__device__ __forceinline__ void cp_wait0()  { asm volatile("cp.async.wait_group 0;"); }

__device__ __forceinline__ void ldsm4(uint32_t* r, uint32_t addr) {
    asm volatile("ldmatrix.sync.aligned.m8n8.x4.shared.b16 {%0,%1,%2,%3}, [%4];"
        : "=r"(r[0]), "=r"(r[1]), "=r"(r[2]), "=r"(r[3]) : "r"(addr));
}
__device__ __forceinline__ void mma_bf16(float* d, const uint32_t* a, const uint32_t* b) {
    asm volatile("mma.sync.aligned.m16n8k16.row.col.f32.bf16.bf16.f32 "
        "{%0,%1,%2,%3},{%4,%5,%6,%7},{%8,%9},{%0,%1,%2,%3};"
        : "+f"(d[0]), "+f"(d[1]), "+f"(d[2]), "+f"(d[3])
        : "r"(a[0]), "r"(a[1]), "r"(a[2]), "r"(a[3]), "r"(b[0]), "r"(b[1]));
}

// ---------------- weight pre-convert (bf16 B image) ----------------
__global__ void convW(const float* __restrict__ Wo1, const float* __restrict__ Wc1) {
    int k = blockIdx.x;
    int n = threadIdx.x;
    int y = n >> 8, nn = n & 255;
    float v = y ? Wc1[k * BN + nn] : Wo1[k * BN + nn];
    __nv_bfloat16 h = __float2bfloat16(v);
    int c = k >> 6, kc = k & 63;
    int ks = kc >> 4, kh = (kc >> 3) & 1, kpos = kc & 7;
    int noct = nn >> 3, r = nn & 7;
    uint32_t off = (uint32_t)(ks * 64 + noct * 2 + kh) * 128 + r * 16 + kpos * 2;
    *(__nv_bfloat16*)&g_W[y][c][off] = h;
}

// ---------------- prototype path ----------------
__global__ void proto1(const float* __restrict__ sf,
                       const float* __restrict__ W1,
                       const float* __restrict__ b1) {
    int s = blockIdx.x;
    int j = blockIdx.y * 64 + (threadIdx.x & 63);
    int kg = threadIdx.x >> 6;
    const float* srow = sf + s * D;
    float acc = 0.f;
    int k0 = kg * 128;
    #pragma unroll 8
    for (int k = k0; k < k0 + 128; k++)
        acc += srow[k] * W1[k * D + j];
    __shared__ float red[PTPB];
    red[threadIdx.x] = acc;
    __syncthreads();
    if (threadIdx.x < 64) {
        float v = red[threadIdx.x] + red[threadIdx.x + 64] + red[threadIdx.x + 128]
                + red[threadIdx.x + 192] + b1[j];
        g_h1[s * D + j] = fmaxf(v, 0.f);
    }
}

__global__ void proto2(const float* __restrict__ W2,
                       const float* __restrict__ b2,
                       float* __restrict__ proto_out) {
    int w = blockIdx.x;
    __shared__ float hsum[D];
    int t = threadIdx.x;
    for (int k = t; k < D; k += PTPB) {
        float a = 0.f;
        #pragma unroll
        for (int s = 0; s < 5; s++) a += g_h1[(w * 5 + s) * D + k];
        hsum[k] = a;
    }
    __syncthreads();
    int j = blockIdx.y * 64 + (t & 63);
    int kg = t >> 6;
    float acc = 0.f;
    int k0 = kg * 128;
    #pragma unroll 8
    for (int k = k0; k < k0 + 128; k++)
        acc += hsum[k] * W2[k * D + j];
    __shared__ float red[PTPB];
    red[t] = acc;
    __syncthreads();
    if (t < 64) {
        float p = (red[t] + red[t + 64] + red[t + 128] + red[t + 192]) * 0.2f + b2[j];
        g_proto[w * D + j] = p;
        #pragma unroll
        for (int kp = 0; kp < NKPTS; kp++)
            proto_out[(size_t)(w * NKPTS + kp) * D + j] = p;
    }
}

// ---------------- preQ: bf16 image transform + exact distances ----------------
__global__ void __launch_bounds__(PTPB, 2)
preQ(const float* __restrict__ Q, const float* __restrict__ temp,
     float* __restrict__ dist_out, float* __restrict__ cls_out) {
    __shared__ float sproto[NWAY * D];
    __shared__ float spn[NWAY];
    __shared__ float sdist[BMP * NWAY];
    __shared__ float scls[BMP];

    const int tid  = threadIdx.x;
    const int warp = tid >> 5;
    const int lane = tid & 31;
    const size_t q0 = (size_t)blockIdx.x * BMP;

    for (int i = tid; i < NWAY * D; i += PTPB) sproto[i] = g_proto[i];
    __syncthreads();

    if (warp < NWAY) {
        float s = 0.f;
        for (int k = lane; k < D; k += 32) { float v = sproto[warp * D + k]; s += v * v; }
        #pragma unroll
        for (int off = 16; off > 0; off >>= 1) s += __shfl_xor_sync(0xffffffffu, s, off);
        if (lane == 0) spn[warp] = sqrtf(s);
    }
    __syncthreads();

    const int rsub = lane >> 2;
    const int lq   = lane & 3;
    uint8_t* img = &g_Qimg[blockIdx.x][0][0];

    #pragma unroll 1
    for (int o = 0; o < 2; o++) {
        int rowl = o * 64 + warp * 8 + rsub;
        const float* qr = Q + (q0 + rowl) * D;
        const int mblk = (rowl >> 4) * 4 + ((rowl >> 3) & 1);
        const int roff = (rowl & 7) * 16 + (lq & 1) * 8;
        const int khb  = (lq >> 1) * 2;

        float qq = 0.f, s0 = 0.f, s1 = 0.f, s2 = 0.f, s3 = 0.f, s4 = 0.f;
        #pragma unroll 8
        for (int j = 0; j < 32; j++) {
            float4 v = ((const float4*)qr)[lq + j * 4];
            int k = lq * 4 + j * 16;
            {
                float4 p0 = *(const float4*)(sproto + 0 * D + k);
                float4 p1 = *(const float4*)(sproto + 1 * D + k);
                float4 p2 = *(const float4*)(sproto + 2 * D + k);
                float4 p3 = *(const float4*)(sproto + 3 * D + k);
                float4 p4 = *(const float4*)(sproto + 4 * D + k);
                qq += v.x * v.x + v.y * v.y + v.z * v.z + v.w * v.w;
                s0 += v.x * p0.x + v.y * p0.y + v.z * p0.z + v.w * p0.w;
                s1 += v.x * p1.x + v.y * p1.y + v.z * p1.z + v.w * p1.w;
                s2 += v.x * p2.x + v.y * p2.y + v.z * p2.z + v.w * p2.w;
                s3 += v.x * p3.x + v.y * p3.y + v.z * p3.z + v.w * p3.w;
                s4 += v.x * p4.x + v.y * p4.y + v.z * p4.z + v.w * p4.w;
            }
            int c = j >> 2;
            uint32_t off = (uint32_t)c * 16384u
                         + (uint32_t)((j & 3) * 32 + khb + mblk) * 128u + roff;
            *(uint2*)(img + off) =
                make_uint2(pack_bf16x2(v.x, v.y), pack_bf16x2(v.z, v.w));
        }

        #pragma unroll
        for (int off = 1; off <= 2; off <<= 1) {
            qq += __shfl_xor_sync(0xffffffffu, qq, off);
            s0 += __shfl_xor_sync(0xffffffffu, s0, off);
            s1 += __shfl_xor_sync(0xffffffffu, s1, off);
            s2 += __shfl_xor_sync(0xffffffffu, s2, off);
            s3 += __shfl_xor_sync(0xffffffffu, s3, off);
            s4 += __shfl_xor_sync(0xffffffffu, s4, off);
        }
        if (lq == 0) {
            const float T = *temp;
            float qn = sqrtf(qq);
            float sv[5] = {s0, s1, s2, s3, s4};
            float best = 3.402823e38f; int bi = 0;
            #pragma unroll
            for (int w = 0; w < NWAY; w++) {
                float denom = fmaxf(qn * spn[w], 1e-8f);
                float dv = (1.0f - sv[w] / denom) / T;
                sdist[rowl * NWAY + w] = dv;
                if (dv < best) { best = dv; bi = w; }
            }
            scls[rowl] = (float)bi;
        }
    }
    __syncthreads();

    for (int rr = 0; rr < 16; rr++) {
        int r = warp * 16 + rr;
        size_t qi = q0 + r;
        for (int l = lane; l < NWAY * NKPTS; l += 32)
            dist_out[qi * (NWAY * NKPTS) + l] = sdist[r * NWAY + l / NKPTS];
        if (lane == 0) cls_out[qi] = scls[r];
    }
}

// ---------------- main GEMM kernel (register-space epilogue) ----------------
__global__ void __launch_bounds__(TPB, 2)
query_kernel(const float* __restrict__ IC,
             const float* __restrict__ bo1, const float* __restrict__ Wo2,
             const float* __restrict__ bo2,
             const float* __restrict__ bc1, const float* __restrict__ Wc2,
             const float* __restrict__ bc2,
             float* __restrict__ kp_out, float* __restrict__ conf_out) {
    extern __shared__ char smem[];
    const uint32_t sb = smem_u32(smem);
    float*  sbias = (float*)(smem + SM_BIAS);
    float*  sW2   = (float*)(smem + SM_W2);
    float2* spart = (float2*)(smem + SM_PART);
    float*  sres  = (float*)(smem + SM_RES);

    const int tid  = threadIdx.x;
    const int warp = tid >> 5;
    const int lane = tid & 31;
    const int g    = lane >> 2;
    const int qd   = lane & 3;
    const int y    = blockIdx.y;
    const int ht   = blockIdx.x;
    const int tile = ht >> 1;
    const int half = ht & 1;
    const size_t q0 = (size_t)ht * BM;

    const uint8_t* Asrc = &g_Qimg[tile][0][0];

    auto cpA = [&](int c, int buf) {
        const uint8_t* src = Asrc + c * 16384;
        char* dst = smem + SM_A + buf * 8192;
        #pragma unroll
        for (int i = 0; i < 2; i++) {
            int idx = tid + i * TPB;
            int run = idx >> 7, w = idx & 127;
            cpa16(dst + run * 2048 + w * 16,
                  src + (uint32_t)(run * 32 + half * 16) * 128 + w * 16);
        }
    };
    auto cpB = [&](int c, int buf) {
        const uint8_t* src = &g_W[y][c][0];
        char* dst = smem + SM_B + buf * 32768;
        #pragma unroll
        for (int i = 0; i < 8; i++) {
            int idx = (tid + i * TPB) * 16;
            cpa16(dst + idx, src + idx);
        }
    };

    // stage epilogue params + prologue loads
    sbias[tid] = y ? bc1[tid] : bo1[tid];
    if (y == 0) { sW2[tid] = Wo2[tid]; sW2[tid + 256] = Wo2[tid + 256]; }
    else        { sW2[tid] = Wc2[tid]; }
    cpA(0, 0);
    cpB(0, 0);
    cp_commit();
    cp_wait0();
    __syncthreads();

    float acc[2][8][4];
    #pragma unroll
    for (int mi = 0; mi < 2; mi++)
        #pragma unroll
        for (int ni = 0; ni < 8; ni++)
            #pragma unroll
            for (int i = 0; i < 4; i++) acc[mi][ni][i] = 0.f;

    const int wm = (warp & 1) * 32;
    const int wn = (warp >> 1) * 64;
    const uint32_t a_mt0 = (uint32_t)((warp & 1) * 2);
    const uint32_t b_blk0 = (uint32_t)(wn >> 2);

    #pragma unroll 1
    for (int c = 0; c < NCH; c++) {
        int buf = c & 1;
        if (c < NCH - 1) {
            cpA(c + 1, buf ^ 1);
            cpB(c + 1, buf ^ 1);
            cp_commit();
        }

        uint32_t ab   = sb + SM_A + buf * 8192;
        uint32_t bbuf = sb + SM_B + buf * 32768;
        #pragma unroll
        for (int ks = 0; ks < 4; ks++) {
            uint32_t Af[2][4];
            #pragma unroll
            for (int j = 0; j < 2; j++)
                ldsm4(Af[j], ab + (uint32_t)(ks * 16 + (a_mt0 + j) * 4) * 128 + lane * 16);
            #pragma unroll
            for (int p = 0; p < 4; p++) {
                uint32_t r[4];
                ldsm4(r, bbuf + (uint32_t)(ks * 64 + b_blk0 + 4 * p) * 128 + lane * 16);
                #pragma unroll
                for (int j = 0; j < 2; j++) {
                    mma_bf16(acc[j][2 * p],     Af[j], r);
                    mma_bf16(acc[j][2 * p + 1], Af[j], r + 2);
                }
            }
        }

        if (c < NCH - 1) {
            cp_wait0();
            __syncthreads();
        }
    }

    // ---- register-space epilogue ----
    // per-thread rows: slot s -> r = wm + (s>>1)*16 + (s&1)*8 + g
    float px[4] = {0.f, 0.f, 0.f, 0.f};
    float py[4] = {0.f, 0.f, 0.f, 0.f};
    #pragma unroll
    for (int mi = 0; mi < 2; mi++) {
        #pragma unroll
        for (int ni = 0; ni < 8; ni++) {
            int col = wn + ni * 8 + 2 * qd;
            float b0 = sbias[col], b1 = sbias[col + 1];
            float h0 = fmaxf(acc[mi][ni][0] + b0, 0.f);
            float h1 = fmaxf(acc[mi][ni][1] + b1, 0.f);
            float h2 = fmaxf(acc[mi][ni][2] + b0, 0.f);
            float h3 = fmaxf(acc[mi][ni][3] + b1, 0.f);
            if (y == 0) {
                float w00 = sW2[2 * col],     w01 = sW2[2 * col + 1];
                float w10 = sW2[2 * col + 2], w11 = sW2[2 * col + 3];
                px[2 * mi]     += h0 * w00 + h1 * w10;
                py[2 * mi]     += h0 * w01 + h1 * w11;
                px[2 * mi + 1] += h2 * w00 + h3 * w10;
                py[2 * mi + 1] += h2 * w01 + h3 * w11;
            } else {
                float w0 = sW2[col], w1 = sW2[col + 1];
                px[2 * mi]     += h0 * w0 + h1 * w1;
                px[2 * mi + 1] += h2 * w0 + h3 * w1;
            }
        }
    }
    #pragma unroll
    for (int off = 1; off <= 2; off <<= 1) {
        #pragma unroll
        for (int s = 0; s < 4; s++) {
            px[s] += __shfl_xor_sync(0xffffffffu, px[s], off);
            py[s] += __shfl_xor_sync(0xffffffffu, py[s], off);
        }
    }
    if (qd == 0) {
        int grp = warp >> 1;
        #pragma unroll
        for (int s = 0; s < 4; s++) {
            int r = wm + (s >> 1) * 16 + (s & 1) * 8 + g;
            spart[r * 4 + grp] = make_float2(px[s], py[s]);
        }
    }
    __syncthreads();

    if (tid < BM) {
        int r = tid;
        float2 a0 = spart[r * 4 + 0], a1 = spart[r * 4 + 1];
        float2 a2 = spart[r * 4 + 2], a3 = spart[r * 4 + 3];
        float ox = a0.x + a1.x + a2.x + a3.x;
        float oy = a0.y + a1.y + a2.y + a3.y;
        size_t qi = q0 + r;
        if (y == 0) {
            ox += bo2[0]; oy += bo2[1];
            sres[2 * r]     = IC[qi * 2 + 0] / (1.0f + expf(-ox));
            sres[2 * r + 1] = IC[qi * 2 + 1] / (1.0f + expf(-oy));
        } else {
            sres[r] = 1.0f / (1.0f + expf(-(ox + bc2[0])));
        }
    }
    __syncthreads();

    // coalesced output writes (warp handles 8 rows)
    if (y == 0) {
        for (int rr = 0; rr < 8; rr++) {
            int r = warp * 8 + rr;
            size_t qi = q0 + r;
            float kx = sres[2 * r], ky = sres[2 * r + 1];
            for (int l = lane; l < 2 * NKPTS; l += 32)
                kp_out[qi * (2 * NKPTS) + l] = (l & 1) ? ky : kx;
        }
    } else {
        for (int rr = 0; rr < 8; rr++) {
            int r = warp * 8 + rr;
            size_t qi = q0 + r;
            if (lane < NKPTS)
                conf_out[qi * NKPTS + lane] = sres[r];
        }
    }
}

extern "C" void kernel_launch(void* const* d_in, const int* in_sizes, int n_in,
                              void* d_out, int out_size) {
    const float* sf   = (const float*)d_in[0];
    const float* Q    = (const float*)d_in[2];
    const float* IC   = (const float*)d_in[3];
    const float* W1   = (const float*)d_in[4];
    const float* b1   = (const float*)d_in[5];
    const float* W2   = (const float*)d_in[6];
    const float* b2   = (const float*)d_in[7];
    const float* Wo1  = (const float*)d_in[8];
    const float* bo1  = (const float*)d_in[9];
    const float* Wo2  = (const float*)d_in[10];
    const float* bo2  = (const float*)d_in[11];
    const float* Wc1  = (const float*)d_in[12];
    const float* bc1  = (const float*)d_in[13];
    const float* Wc2  = (const float*)d_in[14];
    const float* bc2  = (const float*)d_in[15];
    const float* temp = (const float*)d_in[16];

    const int nq = in_sizes[2] / D;

    float* out       = (float*)d_out;
    float* kp_out    = out;
    float* conf_out  = kp_out   + (size_t)nq * 2 * NKPTS;
    float* dist_out  = conf_out + (size_t)nq * NKPTS;
    float* cls_out   = dist_out + (size_t)nq * NWAY * NKPTS;
    float* proto_out = cls_out  + (size_t)nq;

    convW<<<D, 512>>>(Wo1, Wc1);
    proto1<<<dim3(25, 8), PTPB>>>(sf, W1, b1);
    proto2<<<dim3(NWAY, 8), PTPB>>>(W2, b2, proto_out);

    preQ<<<nq / BMP, PTPB>>>(Q, temp, dist_out, cls_out);

    cudaFuncSetAttribute((const void*)query_kernel,
                         cudaFuncAttributeMaxDynamicSharedMemorySize, SM_TOTAL);
    query_kernel<<<dim3(nq / BM, 2), TPB, SM_TOTAL>>>(
        IC, bo1, Wo2, bo2, bc1, Wc2, bc2, kp_out, conf_out);
}